// round 1
// baseline (speedup 1.0000x reference)
#include <cuda_runtime.h>

#define BB 4
#define C 256
#define L 4096
#define EPSV 1e-5f

// ---------------- device scratch (no dynamic allocation allowed) ----------------
__device__ float g_scale[C];                 // gamma * rstd
__device__ float g_shift[C];                 // beta - mean*gamma*rstd
__device__ float g_wf[3][C * C];             // folded wq/wk/wv
__device__ float g_bf[3][C];                 // folded bq/bk/bv
__device__ float g_qkv[3][(size_t)BB * C * L];   // q,k,v  [mat][b][c][l]
__device__ float g_s[(size_t)BB * L * L];        // scores / probs (268 MB)
__device__ float g_h[(size_t)BB * C * L];        // attention output

// ---------------- packed f32x2 FMA (FFMA2) ----------------
union F2U { float2 f; unsigned long long u; };
__device__ __forceinline__ float2 ffma2(float2 a, float2 b, float2 c) {
    F2U ua, ub, uc, ud;
    ua.f = a; ub.f = b; uc.f = c;
    asm("fma.rn.f32x2 %0, %1, %2, %3;" : "=l"(ud.u) : "l"(ua.u), "l"(ub.u), "l"(uc.u));
    return ud.f;
}

// ---------------- 1) BatchNorm statistics per channel ----------------
__global__ void __launch_bounds__(256) bn_stats(const float* __restrict__ x,
                                                const float* __restrict__ gamma,
                                                const float* __restrict__ beta) {
    int c = blockIdx.x, t = threadIdx.x;
    float s = 0.f, sq = 0.f;
    for (int b = 0; b < BB; b++) {
        const float* p = x + ((size_t)b * C + c) * L;
        for (int l = t; l < L; l += 256) {
            float v = p[l];
            s += v;
            sq += v * v;
        }
    }
    __shared__ float sh0[256], sh1[256];
    sh0[t] = s; sh1[t] = sq;
    __syncthreads();
    for (int o = 128; o > 0; o >>= 1) {
        if (t < o) { sh0[t] += sh0[t + o]; sh1[t] += sh1[t + o]; }
        __syncthreads();
    }
    if (t == 0) {
        const float inv_n = 1.f / (float)(BB * L);
        float mean = sh0[0] * inv_n;
        float var  = sh1[0] * inv_n - mean * mean;
        float rs   = rsqrtf(var + EPSV);
        float sc   = gamma[c] * rs;
        g_scale[c] = sc;
        g_shift[c] = beta[c] - mean * sc;
    }
}

// ---------------- 2) fold BN into q/k/v weights ----------------
__global__ void __launch_bounds__(256) fold_weights(const float* __restrict__ wq, const float* __restrict__ bq,
                                                    const float* __restrict__ wk, const float* __restrict__ bk,
                                                    const float* __restrict__ wv, const float* __restrict__ bv) {
    int o = blockIdx.x, mat = blockIdx.y, t = threadIdx.x;
    const float* w  = (mat == 0) ? wq : ((mat == 1) ? wk : wv);
    const float* bb = (mat == 0) ? bq : ((mat == 1) ? bk : bv);
    float wval = w[o * C + t];
    g_wf[mat][o * C + t] = wval * g_scale[t];
    __shared__ float sh[256];
    sh[t] = wval * g_shift[t];
    __syncthreads();
    for (int s2 = 128; s2 > 0; s2 >>= 1) {
        if (t < s2) sh[t] += sh[t + s2];
        __syncthreads();
    }
    if (t == 0) g_bf[mat][o] = bb[o] + sh[0];
}

// ---------------- shared GEMM microkernel body (64x64x16 tile, 4x4/thread) ----------------
#define GEMM_COMPUTE(As, Bs, acc, tx, ty)                                          \
    _Pragma("unroll")                                                              \
    for (int kk = 0; kk < 16; kk++) {                                              \
        float2 a01 = *(const float2*)&As[kk][(ty) * 4];                            \
        float2 a23 = *(const float2*)&As[kk][(ty) * 4 + 2];                        \
        float2 b0  = *(const float2*)&Bs[kk][(tx) * 4];                            \
        float2 b1  = *(const float2*)&Bs[kk][(tx) * 4 + 2];                        \
        float av0 = a01.x, av1 = a01.y, av2 = a23.x, av3 = a23.y;                  \
        acc[0][0] = ffma2(make_float2(av0, av0), b0, acc[0][0]);                   \
        acc[0][1] = ffma2(make_float2(av0, av0), b1, acc[0][1]);                   \
        acc[1][0] = ffma2(make_float2(av1, av1), b0, acc[1][0]);                   \
        acc[1][1] = ffma2(make_float2(av1, av1), b1, acc[1][1]);                   \
        acc[2][0] = ffma2(make_float2(av2, av2), b0, acc[2][0]);                   \
        acc[2][1] = ffma2(make_float2(av2, av2), b1, acc[2][1]);                   \
        acc[3][0] = ffma2(make_float2(av3, av3), b0, acc[3][0]);                   \
        acc[3][1] = ffma2(make_float2(av3, av3), b1, acc[3][1]);                   \
    }

// ---------------- 3) QKV projection: out[o,l] = sum_c W'[o,c] * x[b,c,l] + b' ----------------
__global__ void __launch_bounds__(256) qkv_gemm(const float* __restrict__ x) {
    const int bi  = blockIdx.z & 3;
    const int mat = blockIdx.z >> 2;
    const float* __restrict__ A  = g_wf[mat];
    const float* __restrict__ Bx = x + (size_t)bi * C * L;
    float* __restrict__ Cp = g_qkv[mat] + (size_t)bi * C * L;
    const int m0 = blockIdx.y * 64, n0 = blockIdx.x * 64;

    __shared__ float As[16][66];
    __shared__ float Bs[16][66];
    const int t = threadIdx.x, tx = t & 15, ty = t >> 4;
    float2 acc[4][2];
#pragma unroll
    for (int i = 0; i < 4; i++) { acc[i][0] = make_float2(0.f, 0.f); acc[i][1] = make_float2(0.f, 0.f); }

    for (int k0 = 0; k0 < C; k0 += 16) {
        const int ka = t & 15, ma = t >> 4;
#pragma unroll
        for (int r = 0; r < 4; r++)
            As[ka][ma + 16 * r] = A[(m0 + ma + 16 * r) * C + k0 + ka];
        const int nb = t & 63, kb = t >> 6;
#pragma unroll
        for (int r = 0; r < 4; r++)
            Bs[kb + 4 * r][nb] = Bx[(size_t)(k0 + kb + 4 * r) * L + n0 + nb];
        __syncthreads();
        GEMM_COMPUTE(As, Bs, acc, tx, ty)
        __syncthreads();
    }
#pragma unroll
    for (int i = 0; i < 4; i++) {
        int m = m0 + ty * 4 + i;
        float bias = g_bf[mat][m];
        float4 v = make_float4(acc[i][0].x + bias, acc[i][0].y + bias,
                               acc[i][1].x + bias, acc[i][1].y + bias);
        *(float4*)&Cp[(size_t)m * L + n0 + tx * 4] = v;
    }
}

// ---------------- 4) scores: S[i,j] = scale * sum_c q[c,i] k[c,j] ----------------
__global__ void __launch_bounds__(256) scores_gemm() {
    const int bi = blockIdx.z;
    const float* __restrict__ Q = g_qkv[0] + (size_t)bi * C * L;
    const float* __restrict__ K = g_qkv[1] + (size_t)bi * C * L;
    float* __restrict__ S = g_s + (size_t)bi * L * L;
    const int m0 = blockIdx.y * 64, n0 = blockIdx.x * 64;

    __shared__ float As[16][66];
    __shared__ float Bs[16][66];
    const int t = threadIdx.x, tx = t & 15, ty = t >> 4;
    float2 acc[4][2];
#pragma unroll
    for (int i = 0; i < 4; i++) { acc[i][0] = make_float2(0.f, 0.f); acc[i][1] = make_float2(0.f, 0.f); }

    for (int k0 = 0; k0 < C; k0 += 16) {
        const int na = t & 63, ka = t >> 6;
#pragma unroll
        for (int r = 0; r < 4; r++)
            As[ka + 4 * r][na] = Q[(size_t)(k0 + ka + 4 * r) * L + m0 + na];
#pragma unroll
        for (int r = 0; r < 4; r++)
            Bs[ka + 4 * r][na] = K[(size_t)(k0 + ka + 4 * r) * L + n0 + na];
        __syncthreads();
        GEMM_COMPUTE(As, Bs, acc, tx, ty)
        __syncthreads();
    }
    const float scale = 0.0625f;  // 256^-0.5
#pragma unroll
    for (int i = 0; i < 4; i++) {
        int m = m0 + ty * 4 + i;
        float4 v = make_float4(acc[i][0].x * scale, acc[i][0].y * scale,
                               acc[i][1].x * scale, acc[i][1].y * scale);
        *(float4*)&S[(size_t)m * L + n0 + tx * 4] = v;
    }
}

// ---------------- 5) row softmax (register-resident, one read + one write) ----------------
__global__ void __launch_bounds__(256) softmax_rows() {
    size_t row = blockIdx.x;
    float* p = g_s + row * (size_t)L;
    const int t = threadIdx.x;
    float r[16];
    float mx = -1e30f;
#pragma unroll
    for (int i = 0; i < 16; i++) {
        r[i] = p[t + i * 256];
        mx = fmaxf(mx, r[i]);
    }
#pragma unroll
    for (int o = 16; o; o >>= 1) mx = fmaxf(mx, __shfl_xor_sync(0xffffffffu, mx, o));
    __shared__ float sm[8];
    if ((t & 31) == 0) sm[t >> 5] = mx;
    __syncthreads();
    float bm = sm[0];
#pragma unroll
    for (int i = 1; i < 8; i++) bm = fmaxf(bm, sm[i]);

    float s = 0.f;
#pragma unroll
    for (int i = 0; i < 16; i++) {
        r[i] = __expf(r[i] - bm);
        s += r[i];
    }
#pragma unroll
    for (int o = 16; o; o >>= 1) s += __shfl_xor_sync(0xffffffffu, s, o);
    __syncthreads();
    if ((t & 31) == 0) sm[t >> 5] = s;
    __syncthreads();
    float tot = 0.f;
#pragma unroll
    for (int i = 0; i < 8; i++) tot += sm[i];
    float inv = 1.f / tot;
#pragma unroll
    for (int i = 0; i < 16; i++) p[t + i * 256] = r[i] * inv;
}

// ---------------- 6) AV: H[c,i] = sum_j v[c,j] * P[i,j] ----------------
__global__ void __launch_bounds__(256) av_gemm() {
    const int bi = blockIdx.z;
    const float* __restrict__ V = g_qkv[2] + (size_t)bi * C * L;
    const float* __restrict__ P = g_s + (size_t)bi * L * L;
    float* __restrict__ H = g_h + (size_t)bi * C * L;
    const int m0 = blockIdx.y * 64;  // c
    const int n0 = blockIdx.x * 64;  // i

    __shared__ float As[16][66];
    __shared__ float Bs[16][66];
    const int t = threadIdx.x, tx = t & 15, ty = t >> 4;
    float2 acc[4][2];
#pragma unroll
    for (int i = 0; i < 4; i++) { acc[i][0] = make_float2(0.f, 0.f); acc[i][1] = make_float2(0.f, 0.f); }

    for (int k0 = 0; k0 < L; k0 += 16) {
        const int ka = t & 15, ma = t >> 4;
#pragma unroll
        for (int r = 0; r < 4; r++)
            As[ka][ma + 16 * r] = V[(size_t)(m0 + ma + 16 * r) * L + k0 + ka];
#pragma unroll
        for (int r = 0; r < 4; r++)
            Bs[ka][ma + 16 * r] = P[(size_t)(n0 + ma + 16 * r) * L + k0 + ka];
        __syncthreads();
        GEMM_COMPUTE(As, Bs, acc, tx, ty)
        __syncthreads();
    }
#pragma unroll
    for (int i = 0; i < 4; i++) {
        int m = m0 + ty * 4 + i;
        float4 v = make_float4(acc[i][0].x, acc[i][0].y, acc[i][1].x, acc[i][1].y);
        *(float4*)&H[(size_t)m * L + n0 + tx * 4] = v;
    }
}

// ---------------- 7) output proj + residual ----------------
__global__ void __launch_bounds__(256) proj_gemm(const float* __restrict__ wp,
                                                 const float* __restrict__ bp,
                                                 const float* __restrict__ x,
                                                 float* __restrict__ out) {
    const int bi = blockIdx.z;
    const float* __restrict__ Hh = g_h + (size_t)bi * C * L;
    const int m0 = blockIdx.y * 64, n0 = blockIdx.x * 64;

    __shared__ float As[16][66];
    __shared__ float Bs[16][66];
    const int t = threadIdx.x, tx = t & 15, ty = t >> 4;
    float2 acc[4][2];
#pragma unroll
    for (int i = 0; i < 4; i++) { acc[i][0] = make_float2(0.f, 0.f); acc[i][1] = make_float2(0.f, 0.f); }

    for (int k0 = 0; k0 < C; k0 += 16) {
        const int ka = t & 15, ma = t >> 4;
#pragma unroll
        for (int r = 0; r < 4; r++)
            As[ka][ma + 16 * r] = wp[(m0 + ma + 16 * r) * C + k0 + ka];
        const int nb = t & 63, kb = t >> 6;
#pragma unroll
        for (int r = 0; r < 4; r++)
            Bs[kb + 4 * r][nb] = Hh[(size_t)(k0 + kb + 4 * r) * L + n0 + nb];
        __syncthreads();
        GEMM_COMPUTE(As, Bs, acc, tx, ty)
        __syncthreads();
    }
#pragma unroll
    for (int i = 0; i < 4; i++) {
        int m = m0 + ty * 4 + i;
        float bias = bp[m];
        size_t idx = ((size_t)bi * C + m) * L + n0 + tx * 4;
        float4 xr = *(const float4*)&x[idx];
        float4 v = make_float4(acc[i][0].x + bias + xr.x, acc[i][0].y + bias + xr.y,
                               acc[i][1].x + bias + xr.z, acc[i][1].y + bias + xr.w);
        *(float4*)&out[idx] = v;
    }
}

// ---------------- launch ----------------
extern "C" void kernel_launch(void* const* d_in, const int* in_sizes, int n_in,
                              void* d_out, int out_size) {
    const float* x     = (const float*)d_in[0];
    const float* gamma = (const float*)d_in[1];
    const float* beta  = (const float*)d_in[2];
    const float* wq    = (const float*)d_in[3];
    const float* bq    = (const float*)d_in[4];
    const float* wk    = (const float*)d_in[5];
    const float* bk    = (const float*)d_in[6];
    const float* wv    = (const float*)d_in[7];
    const float* bv    = (const float*)d_in[8];
    const float* wp    = (const float*)d_in[9];
    const float* bp    = (const float*)d_in[10];
    float* out = (float*)d_out;

    bn_stats<<<C, 256>>>(x, gamma, beta);
    fold_weights<<<dim3(C, 3), 256>>>(wq, bq, wk, bk, wv, bv);
    qkv_gemm<<<dim3(L / 64, C / 64, 12), 256>>>(x);
    scores_gemm<<<dim3(L / 64, L / 64, BB), 256>>>();
    softmax_rows<<<BB * L, 256>>>();
    av_gemm<<<dim3(L / 64, C / 64, BB), 256>>>();
    proj_gemm<<<dim3(L / 64, C / 64, BB), 256>>>(wp, bp, x, out);
}

// round 6
// speedup vs baseline: 2.0660x; 2.0660x over previous
#include <cuda_runtime.h>
#include <cuda_bf16.h>
#include <cstdint>

#define BB 4
#define C 256
#define L 4096
#define EPSV 1e-5f

#if defined(__CUDA_ARCH_FEAT_SM103_ALL) || defined(__CUDA_ARCH_FEAT_SM100_ALL) || defined(__CUDA_ARCH_FAMILY_SPECIFIC__)
#define TC_OK 1
#else
#define TC_OK 0
#endif

// ---------------- device scratch ----------------
__device__ float g_scale[C];
__device__ float g_shift[C];
__device__ float g_wf[3][C * C];                  // folded wq/wk/wv (fp32)
__device__ float g_bf[3][C];
__device__ float g_qkv[3][(size_t)BB * C * L];    // fp32 q,k,v  [mat][b][c][l]  (exact)
__device__ float g_h[(size_t)BB * C * L];         // fp32 attention out [b][c][l]
__device__ float g_s[(size_t)BB * L * L];         // fp32 scores
__device__ __align__(16) __nv_bfloat16 g_qh[(size_t)BB * L * C], g_ql[(size_t)BB * L * C]; // qT rows l
__device__ __align__(16) __nv_bfloat16 g_kh[(size_t)BB * L * C], g_kl[(size_t)BB * L * C]; // kT rows l
__device__ __align__(16) __nv_bfloat16 g_vh[(size_t)BB * C * L], g_vl[(size_t)BB * C * L]; // rows c
__device__ __align__(16) __nv_bfloat16 g_ph[(size_t)BB * L * L], g_pl[(size_t)BB * L * L]; // rows i

// ---------------- SMEM layout for TC GEMMs ----------------
#define SM_PTR   0
#define SM_MBAR0 8
#define SM_MBAR1 16
#define SM_A     1024
#define SM_B     (1024 + 32768)
#define SMEMSZ   (1024 + 32768 + 65536)

// idesc kind::f16: c=F32, a=BF16, b=BF16, N=256, M=128
#define IDESC_BF16 0x8400490u

// ---------------- packed f32x2 FMA (R1 FFMA path) ----------------
union F2U { float2 f; unsigned long long u; };
__device__ __forceinline__ float2 ffma2(float2 a, float2 b, float2 c) {
    F2U ua, ub, uc, ud;
    ua.f = a; ub.f = b; uc.f = c;
    asm("fma.rn.f32x2 %0, %1, %2, %3;" : "=l"(ud.u) : "l"(ua.u), "l"(ub.u), "l"(uc.u));
    return ud.f;
}

#define GEMM_COMPUTE(As, Bs, acc, tx, ty)                                          \
    _Pragma("unroll")                                                              \
    for (int kk = 0; kk < 16; kk++) {                                              \
        float2 a01 = *(const float2*)&As[kk][(ty) * 4];                            \
        float2 a23 = *(const float2*)&As[kk][(ty) * 4 + 2];                        \
        float2 b0  = *(const float2*)&Bs[kk][(tx) * 4];                            \
        float2 b1  = *(const float2*)&Bs[kk][(tx) * 4 + 2];                        \
        float av0 = a01.x, av1 = a01.y, av2 = a23.x, av3 = a23.y;                  \
        acc[0][0] = ffma2(make_float2(av0, av0), b0, acc[0][0]);                   \
        acc[0][1] = ffma2(make_float2(av0, av0), b1, acc[0][1]);                   \
        acc[1][0] = ffma2(make_float2(av1, av1), b0, acc[1][0]);                   \
        acc[1][1] = ffma2(make_float2(av1, av1), b1, acc[1][1]);                   \
        acc[2][0] = ffma2(make_float2(av2, av2), b0, acc[2][0]);                   \
        acc[2][1] = ffma2(make_float2(av2, av2), b1, acc[2][1]);                   \
        acc[3][0] = ffma2(make_float2(av3, av3), b0, acc[3][0]);                   \
        acc[3][1] = ffma2(make_float2(av3, av3), b1, acc[3][1]);                   \
    }

// ---------------- fold-proof bf16 hi/lo split (pure PTX) ----------------
__device__ __forceinline__ void split_bf16(float v, uint16_t& hb, uint16_t& lb) {
    float hf, r;
    asm("cvt.rn.bf16.f32 %0, %1;" : "=h"(hb) : "f"(v));
    asm("cvt.f32.bf16 %0, %1;"    : "=f"(hf) : "h"(hb));
    asm("sub.rn.f32 %0, %1, %2;"  : "=f"(r)  : "f"(v), "f"(hf));
    asm("cvt.rn.bf16.f32 %0, %1;" : "=h"(lb) : "f"(r));
}
__device__ __forceinline__ void wsplit2(__nv_bfloat16* h, __nv_bfloat16* l, size_t idx,
                                        float a, float b) {
    uint16_t ha, la, hbb, lbb;
    split_bf16(a, ha, la);
    split_bf16(b, hbb, lbb);
    uint32_t hp = (uint32_t)ha | ((uint32_t)hbb << 16);
    uint32_t lp = (uint32_t)la | ((uint32_t)lbb << 16);
    *(uint32_t*)((char*)h + idx * 2) = hp;
    *(uint32_t*)((char*)l + idx * 2) = lp;
}

// ---------------- tcgen05 helpers ----------------
__device__ __forceinline__ uint32_t smem_u32(const void* p) {
    uint32_t a;
    asm("{ .reg .u64 t; cvta.to.shared.u64 t, %1; cvt.u32.u64 %0, t; }" : "=r"(a) : "l"(p));
    return a;
}
__device__ __forceinline__ uint32_t elect1() {
    uint32_t p;
    asm volatile("{\n\t.reg .pred p;\n\telect.sync _|p, 0xFFFFFFFF;\n\tselp.b32 %0, 1, 0, p;\n\t}" : "=r"(p));
    return p;
}
__device__ __forceinline__ uint64_t make_desc(uint32_t addr) {
    return (2ULL << 61) | (1ULL << 46) | (64ULL << 32) | (1ULL << 16) |
           ((uint64_t)(addr >> 4) & 0x3FFF);
}
__device__ __forceinline__ void tc_alloc(uint32_t sptr) {
#if TC_OK
    asm volatile("tcgen05.alloc.cta_group::1.sync.aligned.shared::cta.b32 [%0], %1;"
                 :: "r"(sptr), "r"(256u) : "memory");
    asm volatile("tcgen05.relinquish_alloc_permit.cta_group::1.sync.aligned;");
#endif
}
__device__ __forceinline__ void tc_dealloc(uint32_t tmem) {
#if TC_OK
    asm volatile("tcgen05.dealloc.cta_group::1.sync.aligned.b32 %0, %1;" :: "r"(tmem), "r"(256u));
#endif
}
__device__ __forceinline__ void mma_bf16(uint32_t d, uint64_t ad, uint64_t bd, bool acc) {
#if TC_OK
    uint32_t e = acc ? 1u : 0u;
    asm volatile(
        "{\n\t.reg .pred p;\n\tsetp.ne.u32 p, %4, 0;\n\t"
        "tcgen05.mma.cta_group::1.kind::f16 [%0], %1, %2, %3, {%5, %5, %5, %5}, p;\n\t}"
        :: "r"(d), "l"(ad), "l"(bd), "r"(IDESC_BF16), "r"(e), "r"(0u) : "memory");
#endif
}
__device__ __forceinline__ void tc_commit(uint32_t mbar) {
#if TC_OK
    asm volatile("tcgen05.commit.cta_group::1.mbarrier::arrive::one.shared::cluster.b64 [%0];"
                 :: "r"(mbar) : "memory");
#endif
}
__device__ __forceinline__ void tc_fence_after() {
#if TC_OK
    asm volatile("tcgen05.fence::after_thread_sync;" ::: "memory");
#endif
}
__device__ __forceinline__ void ldtm32(uint32_t* r, uint32_t addr) {
#if TC_OK
    asm volatile(
        "tcgen05.ld.sync.aligned.32x32b.x32.b32 "
        "{%0, %1, %2, %3, %4, %5, %6, %7, "
        " %8, %9, %10, %11, %12, %13, %14, %15, "
        " %16, %17, %18, %19, %20, %21, %22, %23, "
        " %24, %25, %26, %27, %28, %29, %30, %31}, [%32];"
        : "=r"(r[0]),  "=r"(r[1]),  "=r"(r[2]),  "=r"(r[3]),
          "=r"(r[4]),  "=r"(r[5]),  "=r"(r[6]),  "=r"(r[7]),
          "=r"(r[8]),  "=r"(r[9]),  "=r"(r[10]), "=r"(r[11]),
          "=r"(r[12]), "=r"(r[13]), "=r"(r[14]), "=r"(r[15]),
          "=r"(r[16]), "=r"(r[17]), "=r"(r[18]), "=r"(r[19]),
          "=r"(r[20]), "=r"(r[21]), "=r"(r[22]), "=r"(r[23]),
          "=r"(r[24]), "=r"(r[25]), "=r"(r[26]), "=r"(r[27]),
          "=r"(r[28]), "=r"(r[29]), "=r"(r[30]), "=r"(r[31])
        : "r"(addr));
    asm volatile("tcgen05.wait::ld.sync.aligned;" ::: "memory");
#else
#pragma unroll
    for (int i = 0; i < 32; i++) r[i] = 0;
#endif
}
__device__ __forceinline__ void mbar_init(uint32_t a) {
    asm volatile("mbarrier.init.shared.b64 [%0], %1;" :: "r"(a), "r"(1u) : "memory");
}
__device__ __forceinline__ void mbar_wait(uint32_t a, int parity) {
    asm volatile(
        "{\n\t.reg .pred P;\n"
        "W_%=:\n\t"
        "mbarrier.try_wait.parity.acquire.cta.shared::cta.b64 P, [%0], %1, 0x989680;\n\t"
        "@P bra.uni D_%=;\n\t"
        "bra.uni W_%=;\n"
        "D_%=:\n\t}"
        :: "r"(a), "r"(parity) : "memory");
}

// ---------------- TC tile loader (SW128) ----------------
__device__ __forceinline__ void load_tiles(const __nv_bfloat16* __restrict__ A, int lda,
                                           const __nv_bfloat16* __restrict__ B, int ldb,
                                           int k0, char* da, char* db, int t) {
#pragma unroll
    for (int i = 0; i < 8; i++) {
        int idx = t + i * 128;
        int r = idx >> 3, cc = idx & 7;
        float4 v = *(const float4*)(A + (size_t)r * lda + k0 + cc * 8);
        uint32_t off = r * 128 + cc * 16;
        *(float4*)(da + (off ^ ((off >> 3) & 0x70))) = v;
    }
#pragma unroll
    for (int i = 0; i < 16; i++) {
        int idx = t + i * 128;
        int r = idx >> 3, cc = idx & 7;
        float4 v = *(const float4*)(B + (size_t)r * ldb + k0 + cc * 8);
        uint32_t off = r * 128 + cc * 16;
        *(float4*)(db + (off ^ ((off >> 3) & 0x70))) = v;
    }
}

__device__ __forceinline__ void seg_sel(const __nv_bfloat16* Ah, const __nv_bfloat16* Al,
                                        const __nv_bfloat16* Bh, const __nv_bfloat16* Bl,
                                        int ck, int nseg,
                                        const __nv_bfloat16*& Ap, const __nv_bfloat16*& Bp, int& k0) {
    int seg = (ck >= nseg) + (ck >= 2 * nseg);
    Ap = (seg == 1) ? Al : Ah;
    Bp = (seg == 2) ? Bl : Bh;
    k0 = (ck - seg * nseg) * 64;
}

// D[128x256] = Ah*Bh^T + Al*Bh^T + Ah*Bl^T
__device__ __forceinline__ uint32_t run_gemm3(const __nv_bfloat16* __restrict__ Ah,
                                              const __nv_bfloat16* __restrict__ Al,
                                              const __nv_bfloat16* __restrict__ Bh,
                                              const __nv_bfloat16* __restrict__ Bl,
                                              int lda, int ldb, int nseg, char* smem) {
    const int t = threadIdx.x;
    const int nch = 3 * nseg;
    uint32_t sb = smem_u32(smem);
    if (t < 32) tc_alloc(sb + SM_PTR);
    if (t == 0) { mbar_init(sb + SM_MBAR0); mbar_init(sb + SM_MBAR1); }
    __syncthreads();
    uint32_t tmem;
    asm volatile("ld.shared.b32 %0, [%1];" : "=r"(tmem) : "r"(sb + SM_PTR));

    int ph0 = 0, ph1 = 0;
    load_tiles(Ah, lda, Bh, ldb, 0, smem + SM_A, smem + SM_B, t);
    __syncthreads();

    for (int ck = 0; ck < nch; ck++) {
        const int pb = ck & 1;
        if (t < 32) {
            asm volatile("fence.proxy.async.shared::cta;" ::: "memory");
            if (elect1()) {
                uint64_t ad = make_desc(sb + SM_A + pb * 16384);
                uint64_t bd = make_desc(sb + SM_B + pb * 32768);
#pragma unroll
                for (int s = 0; s < 4; s++)
                    mma_bf16(tmem, ad + 2 * s, bd + 2 * s, (ck | s) != 0);
                tc_commit(sb + SM_MBAR0 + pb * 8);
            }
        }
        if (ck + 1 < nch) {
            const int nb2 = pb ^ 1;
            if (ck >= 1) {
                if (nb2 == 0) { mbar_wait(sb + SM_MBAR0, ph0); ph0 ^= 1; }
                else          { mbar_wait(sb + SM_MBAR1, ph1); ph1 ^= 1; }
            }
            const __nv_bfloat16 *Ap, *Bp;
            int k0;
            seg_sel(Ah, Al, Bh, Bl, ck + 1, nseg, Ap, Bp, k0);
            load_tiles(Ap, lda, Bp, ldb, k0,
                       smem + SM_A + nb2 * 16384, smem + SM_B + nb2 * 32768, t);
        }
        __syncthreads();
    }
    if (((nch - 1) & 1) == 0) mbar_wait(sb + SM_MBAR0, ph0);
    else                      mbar_wait(sb + SM_MBAR1, ph1);
    tc_fence_after();
    return tmem;
}

__device__ __forceinline__ void gemm_dealloc(uint32_t tmem) {
    __syncthreads();
    if (threadIdx.x < 32) tc_dealloc(tmem);
}

// ---------------- 1) BN stats ----------------
__global__ void __launch_bounds__(256) bn_stats(const float* __restrict__ x,
                                                const float* __restrict__ gamma,
                                                const float* __restrict__ beta) {
    int c = blockIdx.x, t = threadIdx.x;
    float s = 0.f, sq = 0.f;
    for (int b = 0; b < BB; b++) {
        const float* p = x + ((size_t)b * C + c) * L;
        for (int l = t; l < L; l += 256) { float v = p[l]; s += v; sq += v * v; }
    }
    __shared__ float sh0[256], sh1[256];
    sh0[t] = s; sh1[t] = sq;
    __syncthreads();
    for (int o = 128; o > 0; o >>= 1) {
        if (t < o) { sh0[t] += sh0[t + o]; sh1[t] += sh1[t + o]; }
        __syncthreads();
    }
    if (t == 0) {
        const float inv_n = 1.f / (float)(BB * L);
        float mean = sh0[0] * inv_n;
        float var  = sh1[0] * inv_n - mean * mean;
        float rs   = rsqrtf(var + EPSV);
        float sc   = gamma[c] * rs;
        g_scale[c] = sc;
        g_shift[c] = beta[c] - mean * sc;
    }
}

// ---------------- 2) fold BN into q/k/v weights (fp32) ----------------
__global__ void __launch_bounds__(256) fold_weights(const float* __restrict__ wq, const float* __restrict__ bq,
                                                    const float* __restrict__ wk, const float* __restrict__ bk,
                                                    const float* __restrict__ wv, const float* __restrict__ bv) {
    int o = blockIdx.x, mat = blockIdx.y, t = threadIdx.x;
    const float* w  = (mat == 0) ? wq : ((mat == 1) ? wk : wv);
    const float* bb = (mat == 0) ? bq : ((mat == 1) ? bk : bv);
    float wval = w[o * C + t];
    g_wf[mat][o * C + t] = wval * g_scale[t];
    __shared__ float sh[256];
    sh[t] = wval * g_shift[t];
    __syncthreads();
    for (int s2 = 128; s2 > 0; s2 >>= 1) {
        if (t < s2) sh[t] += sh[t + s2];
        __syncthreads();
    }
    if (t == 0) g_bf[mat][o] = bb[o] + sh[0];
}

// ---------------- 3) QKV projection, fp32 FFMA (exact) ----------------
__global__ void __launch_bounds__(256) qkv_gemm(const float* __restrict__ x) {
    const int bi  = blockIdx.z & 3;
    const int mat = blockIdx.z >> 2;
    const float* __restrict__ A  = g_wf[mat];
    const float* __restrict__ Bx = x + (size_t)bi * C * L;
    float* __restrict__ Cp = g_qkv[mat] + (size_t)bi * C * L;
    const int m0 = blockIdx.y * 64, n0 = blockIdx.x * 64;

    __shared__ float As[16][66];
    __shared__ float Bs[16][66];
    const int t = threadIdx.x, tx = t & 15, ty = t >> 4;
    float2 acc[4][2];
#pragma unroll
    for (int i = 0; i < 4; i++) { acc[i][0] = make_float2(0.f, 0.f); acc[i][1] = make_float2(0.f, 0.f); }

    for (int k0 = 0; k0 < C; k0 += 16) {
        const int ka = t & 15, ma = t >> 4;
#pragma unroll
        for (int r = 0; r < 4; r++)
            As[ka][ma + 16 * r] = A[(m0 + ma + 16 * r) * C + k0 + ka];
        const int nb = t & 63, kb = t >> 6;
#pragma unroll
        for (int r = 0; r < 4; r++)
            Bs[kb + 4 * r][nb] = Bx[(size_t)(k0 + kb + 4 * r) * L + n0 + nb];
        __syncthreads();
        GEMM_COMPUTE(As, Bs, acc, tx, ty)
        __syncthreads();
    }
#pragma unroll
    for (int i = 0; i < 4; i++) {
        int m = m0 + ty * 4 + i;
        float bias = g_bf[mat][m];
        float4 v = make_float4(acc[i][0].x + bias, acc[i][0].y + bias,
                               acc[i][1].x + bias, acc[i][1].y + bias);
        *(float4*)&Cp[(size_t)m * L + n0 + tx * 4] = v;
    }
}

// ---------------- 4) transpose + split q,k -> rows-l hi/lo ----------------
__global__ void __launch_bounds__(256) transpose_split_qk() {
    __shared__ float tile[32][33];
    int bi = blockIdx.z >> 1, mat = blockIdx.z & 1;
    int l0 = blockIdx.x * 32, c0 = blockIdx.y * 32;
    int tx = threadIdx.x, ty = threadIdx.y;
    const float* src = g_qkv[mat] + (size_t)bi * C * L;
#pragma unroll
    for (int j = 0; j < 4; j++)
        tile[ty + j * 8][tx] = src[(size_t)(c0 + ty + j * 8) * L + l0 + tx];
    __syncthreads();
    __nv_bfloat16* dh = mat ? g_kh : g_qh;
    __nv_bfloat16* dl = mat ? g_kl : g_ql;
#pragma unroll
    for (int j = 0; j < 4; j++) {
        int l = l0 + ty + j * 8;
        float v = tile[tx][ty + j * 8];
        uint16_t hb, lb;
        split_bf16(v, hb, lb);
        size_t idx = ((size_t)bi * L + l) * C + c0 + tx;
        *(uint16_t*)&dh[idx] = hb;
        *(uint16_t*)&dl[idx] = lb;
    }
}

// ---------------- 5) split v (elementwise, layout [c][l] kept) ----------------
__global__ void __launch_bounds__(256) split_v() {
    size_t i = ((size_t)blockIdx.x * 256 + threadIdx.x) * 2;
    float2 v = *(const float2*)(g_qkv[2] + i);
    wsplit2(g_vh, g_vl, i, v.x, v.y);
}

// ---------------- 6) scores TC: S[i,j] fp32 ----------------
__global__ void __launch_bounds__(128) scores_gemm_tc() {
    extern __shared__ char smem[];
    int bi = blockIdx.z, i0 = blockIdx.y * 128, j0 = blockIdx.x * 256;
    size_t arow = ((size_t)bi * L + i0) * C;
    size_t brow = ((size_t)bi * L + j0) * C;
    uint32_t tmem = run_gemm3(g_qh + arow, g_ql + arow, g_kh + brow, g_kl + brow, C, C, 4, smem);

    int t = threadIdx.x;
    float* dst = g_s + ((size_t)bi * L + i0 + t) * L + j0;
    const float scale = 0.0625f;
    for (int nb = 0; nb < 8; nb++) {
        uint32_t r[32];
        ldtm32(r, tmem + nb * 32);
#pragma unroll
        for (int j = 0; j < 8; j++) {
            float4 v;
            v.x = __uint_as_float(r[4 * j + 0]) * scale;
            v.y = __uint_as_float(r[4 * j + 1]) * scale;
            v.z = __uint_as_float(r[4 * j + 2]) * scale;
            v.w = __uint_as_float(r[4 * j + 3]) * scale;
            *(float4*)(dst + nb * 32 + 4 * j) = v;
        }
    }
    gemm_dealloc(tmem);
}

// ---------------- 7) softmax rows -> ph/pl ----------------
__global__ void __launch_bounds__(256) softmax_rows() {
    size_t row = blockIdx.x;
    const float* p = g_s + row * (size_t)L;
    const int t = threadIdx.x;
    float2 r[8];
    float mx = -1e30f;
#pragma unroll
    for (int i = 0; i < 8; i++) {
        r[i] = *(const float2*)(p + i * 512 + t * 2);
        mx = fmaxf(mx, fmaxf(r[i].x, r[i].y));
    }
#pragma unroll
    for (int o = 16; o; o >>= 1) mx = fmaxf(mx, __shfl_xor_sync(0xffffffffu, mx, o));
    __shared__ float sm[8];
    if ((t & 31) == 0) sm[t >> 5] = mx;
    __syncthreads();
    float bm = sm[0];
#pragma unroll
    for (int i = 1; i < 8; i++) bm = fmaxf(bm, sm[i]);
    float s = 0.f;
#pragma unroll
    for (int i = 0; i < 8; i++) {
        r[i].x = __expf(r[i].x - bm);
        r[i].y = __expf(r[i].y - bm);
        s += r[i].x + r[i].y;
    }
#pragma unroll
    for (int o = 16; o; o >>= 1) s += __shfl_xor_sync(0xffffffffu, s, o);
    __syncthreads();
    if ((t & 31) == 0) sm[t >> 5] = s;
    __syncthreads();
    float tot = 0.f;
#pragma unroll
    for (int i = 0; i < 8; i++) tot += sm[i];
    float inv = 1.f / tot;
    size_t base = row * (size_t)L;
#pragma unroll
    for (int i = 0; i < 8; i++)
        wsplit2(g_ph, g_pl, base + i * 512 + t * 2, r[i].x * inv, r[i].y * inv);
}

// ---------------- 8) AV TC: writes fp32 h[c][l] (transposed epilogue) ----------------
__global__ void __launch_bounds__(128) av_gemm_tc() {
    extern __shared__ char smem[];
    int bi = blockIdx.y, i0 = blockIdx.x * 128;
    size_t arow = ((size_t)bi * L + i0) * L;
    size_t brow = (size_t)bi * C * L;
    uint32_t tmem = run_gemm3(g_ph + arow, g_pl + arow, g_vh + brow, g_vl + brow, L, L, 64, smem);

    int t = threadIdx.x;  // row i = i0 + t
    float* hb = g_h + (size_t)bi * C * L;
    for (int nb = 0; nb < 8; nb++) {
        uint32_t r[32];
        ldtm32(r, tmem + nb * 32);
#pragma unroll
        for (int j = 0; j < 32; j++) {
            int c = nb * 32 + j;
            hb[(size_t)c * L + i0 + t] = __uint_as_float(r[j]);  // coalesced across t
        }
    }
    gemm_dealloc(tmem);
}

// ---------------- 9) output proj + residual, fp32 FFMA (exact) ----------------
__global__ void __launch_bounds__(256) proj_gemm(const float* __restrict__ wp,
                                                 const float* __restrict__ bp,
                                                 const float* __restrict__ x,
                                                 float* __restrict__ out) {
    const int bi = blockIdx.z;
    const float* __restrict__ Hh = g_h + (size_t)bi * C * L;
    const int m0 = blockIdx.y * 64, n0 = blockIdx.x * 64;

    __shared__ float As[16][66];
    __shared__ float Bs[16][66];
    const int t = threadIdx.x, tx = t & 15, ty = t >> 4;
    float2 acc[4][2];
#pragma unroll
    for (int i = 0; i < 4; i++) { acc[i][0] = make_float2(0.f, 0.f); acc[i][1] = make_float2(0.f, 0.f); }

    for (int k0 = 0; k0 < C; k0 += 16) {
        const int ka = t & 15, ma = t >> 4;
#pragma unroll
        for (int r = 0; r < 4; r++)
            As[ka][ma + 16 * r] = wp[(m0 + ma + 16 * r) * C + k0 + ka];
        const int nb = t & 63, kb = t >> 6;
#pragma unroll
        for (int r = 0; r < 4; r++)
            Bs[kb + 4 * r][nb] = Hh[(size_t)(k0 + kb + 4 * r) * L + n0 + nb];
        __syncthreads();
        GEMM_COMPUTE(As, Bs, acc, tx, ty)
        __syncthreads();
    }
#pragma unroll
    for (int i = 0; i < 4; i++) {
        int m = m0 + ty * 4 + i;
        float bias = bp[m];
        size_t idx = ((size_t)bi * C + m) * L + n0 + tx * 4;
        float4 xr = *(const float4*)&x[idx];
        float4 v = make_float4(acc[i][0].x + bias + xr.x, acc[i][0].y + bias + xr.y,
                               acc[i][1].x + bias + xr.z, acc[i][1].y + bias + xr.w);
        *(float4*)&out[idx] = v;
    }
}

// ---------------- launch ----------------
extern "C" void kernel_launch(void* const* d_in, const int* in_sizes, int n_in,
                              void* d_out, int out_size) {
    const float* x     = (const float*)d_in[0];
    const float* gamma = (const float*)d_in[1];
    const float* beta  = (const float*)d_in[2];
    const float* wq    = (const float*)d_in[3];
    const float* bq    = (const float*)d_in[4];
    const float* wk    = (const float*)d_in[5];
    const float* bk    = (const float*)d_in[6];
    const float* wv    = (const float*)d_in[7];
    const float* bv    = (const float*)d_in[8];
    const float* wp    = (const float*)d_in[9];
    const float* bp    = (const float*)d_in[10];
    float* out = (float*)d_out;

    cudaFuncSetAttribute(scores_gemm_tc, cudaFuncAttributeMaxDynamicSharedMemorySize, SMEMSZ);
    cudaFuncSetAttribute(av_gemm_tc,     cudaFuncAttributeMaxDynamicSharedMemorySize, SMEMSZ);

    bn_stats<<<C, 256>>>(x, gamma, beta);
    fold_weights<<<dim3(C, 3), 256>>>(wq, bq, wk, bk, wv, bv);
    qkv_gemm<<<dim3(L / 64, C / 64, 12), 256>>>(x);
    transpose_split_qk<<<dim3(L / 32, C / 32, BB * 2), dim3(32, 8)>>>();
    split_v<<<(int)(((size_t)BB * C * L / 2) / 256), 256>>>();
    scores_gemm_tc<<<dim3(L / 256, L / 128, BB), 128, SMEMSZ>>>();
    softmax_rows<<<BB * L, 256>>>();
    av_gemm_tc<<<dim3(L / 128, BB), 128, SMEMSZ>>>();
    proj_gemm<<<dim3(L / 64, C / 64, BB), 256>>>(wp, bp, x, out);
}

// round 8
// speedup vs baseline: 2.3369x; 1.1311x over previous
#include <cuda_runtime.h>
#include <cuda_bf16.h>
#include <cstdint>

#define BB 4
#define C 256
#define L 4096
#define EPSV 1e-5f

#if defined(__CUDA_ARCH_FEAT_SM103_ALL) || defined(__CUDA_ARCH_FEAT_SM100_ALL) || defined(__CUDA_ARCH_FAMILY_SPECIFIC__)
#define TC_OK 1
#else
#define TC_OK 0
#endif

// ---------------- device scratch ----------------
__device__ float g_scale[C];
__device__ float g_shift[C];
__device__ __align__(16) __nv_bfloat16 g_wbh[4 * C * C], g_wbl[4 * C * C];   // RAW weights, split
__device__ __align__(16) __nv_bfloat16 g_xth[(size_t)BB * L * C], g_xtl[(size_t)BB * L * C]; // normalized xT rows l
__device__ float g_qT[(size_t)BB * L * C];        // fp32 qT rows l
__device__ float g_kT[(size_t)BB * L * C];        // fp32 kT rows l
__device__ float g_vf[(size_t)BB * C * L];        // fp32 v [c][l]
__device__ float g_h[(size_t)BB * C * L];         // fp32 attn out [c][l]
__device__ float g_s[(size_t)BB * L * L];         // fp32 scores
__device__ __align__(16) __nv_bfloat16 g_qh[(size_t)BB * L * C], g_ql[(size_t)BB * L * C];
__device__ __align__(16) __nv_bfloat16 g_kh[(size_t)BB * L * C], g_kl[(size_t)BB * L * C];
__device__ __align__(16) __nv_bfloat16 g_vh[(size_t)BB * C * L], g_vl[(size_t)BB * C * L];
__device__ __align__(16) __nv_bfloat16 g_ph[(size_t)BB * L * L], g_pl[(size_t)BB * L * L];
__device__ __align__(16) __nv_bfloat16 g_hth[(size_t)BB * L * C], g_htl[(size_t)BB * L * C]; // hT rows l

// ---------------- SMEM layout for TC GEMMs ----------------
#define SM_PTR   0
#define SM_MBAR0 8
#define SM_MBAR1 16
#define SM_A     1024
#define SM_B     (1024 + 32768)
#define SMEMSZ   (1024 + 32768 + 65536)

// idesc kind::f16: c=F32, a=BF16, b=BF16, N=256, M=128
#define IDESC_BF16 0x8400490u

// ---------------- fold-proof bf16 hi/lo split (pure PTX) ----------------
__device__ __forceinline__ void split_bf16(float v, uint16_t& hb, uint16_t& lb) {
    float hf, r;
    asm("cvt.rn.bf16.f32 %0, %1;" : "=h"(hb) : "f"(v));
    asm("cvt.f32.bf16 %0, %1;"    : "=f"(hf) : "h"(hb));
    asm("sub.rn.f32 %0, %1, %2;"  : "=f"(r)  : "f"(v), "f"(hf));
    asm("cvt.rn.bf16.f32 %0, %1;" : "=h"(lb) : "f"(r));
}
__device__ __forceinline__ void wsplit2(__nv_bfloat16* h, __nv_bfloat16* l, size_t idx,
                                        float a, float b) {
    uint16_t ha, la, hbb, lbb;
    split_bf16(a, ha, la);
    split_bf16(b, hbb, lbb);
    uint32_t hp = (uint32_t)ha | ((uint32_t)hbb << 16);
    uint32_t lp = (uint32_t)la | ((uint32_t)lbb << 16);
    *(uint32_t*)((char*)h + idx * 2) = hp;
    *(uint32_t*)((char*)l + idx * 2) = lp;
}

// ---------------- tcgen05 helpers ----------------
__device__ __forceinline__ uint32_t smem_u32(const void* p) {
    uint32_t a;
    asm("{ .reg .u64 t; cvta.to.shared.u64 t, %1; cvt.u32.u64 %0, t; }" : "=r"(a) : "l"(p));
    return a;
}
__device__ __forceinline__ uint32_t elect1() {
    uint32_t p;
    asm volatile("{\n\t.reg .pred p;\n\telect.sync _|p, 0xFFFFFFFF;\n\tselp.b32 %0, 1, 0, p;\n\t}" : "=r"(p));
    return p;
}
__device__ __forceinline__ uint64_t make_desc(uint32_t addr) {
    return (2ULL << 61) | (1ULL << 46) | (64ULL << 32) | (1ULL << 16) |
           ((uint64_t)(addr >> 4) & 0x3FFF);
}
__device__ __forceinline__ void tc_alloc(uint32_t sptr) {
#if TC_OK
    asm volatile("tcgen05.alloc.cta_group::1.sync.aligned.shared::cta.b32 [%0], %1;"
                 :: "r"(sptr), "r"(256u) : "memory");
    asm volatile("tcgen05.relinquish_alloc_permit.cta_group::1.sync.aligned;");
#endif
}
__device__ __forceinline__ void tc_dealloc(uint32_t tmem) {
#if TC_OK
    asm volatile("tcgen05.dealloc.cta_group::1.sync.aligned.b32 %0, %1;" :: "r"(tmem), "r"(256u));
#endif
}
__device__ __forceinline__ void mma_bf16(uint32_t d, uint64_t ad, uint64_t bd, bool acc) {
#if TC_OK
    uint32_t e = acc ? 1u : 0u;
    asm volatile(
        "{\n\t.reg .pred p;\n\tsetp.ne.u32 p, %4, 0;\n\t"
        "tcgen05.mma.cta_group::1.kind::f16 [%0], %1, %2, %3, {%5, %5, %5, %5}, p;\n\t}"
        :: "r"(d), "l"(ad), "l"(bd), "r"(IDESC_BF16), "r"(e), "r"(0u) : "memory");
#endif
}
__device__ __forceinline__ void tc_commit(uint32_t mbar) {
#if TC_OK
    asm volatile("tcgen05.commit.cta_group::1.mbarrier::arrive::one.shared::cluster.b64 [%0];"
                 :: "r"(mbar) : "memory");
#endif
}
__device__ __forceinline__ void tc_fence_after() {
#if TC_OK
    asm volatile("tcgen05.fence::after_thread_sync;" ::: "memory");
#endif
}
__device__ __forceinline__ void ldtm32(uint32_t* r, uint32_t addr) {
#if TC_OK
    asm volatile(
        "tcgen05.ld.sync.aligned.32x32b.x32.b32 "
        "{%0, %1, %2, %3, %4, %5, %6, %7, "
        " %8, %9, %10, %11, %12, %13, %14, %15, "
        " %16, %17, %18, %19, %20, %21, %22, %23, "
        " %24, %25, %26, %27, %28, %29, %30, %31}, [%32];"
        : "=r"(r[0]),  "=r"(r[1]),  "=r"(r[2]),  "=r"(r[3]),
          "=r"(r[4]),  "=r"(r[5]),  "=r"(r[6]),  "=r"(r[7]),
          "=r"(r[8]),  "=r"(r[9]),  "=r"(r[10]), "=r"(r[11]),
          "=r"(r[12]), "=r"(r[13]), "=r"(r[14]), "=r"(r[15]),
          "=r"(r[16]), "=r"(r[17]), "=r"(r[18]), "=r"(r[19]),
          "=r"(r[20]), "=r"(r[21]), "=r"(r[22]), "=r"(r[23]),
          "=r"(r[24]), "=r"(r[25]), "=r"(r[26]), "=r"(r[27]),
          "=r"(r[28]), "=r"(r[29]), "=r"(r[30]), "=r"(r[31])
        : "r"(addr));
    asm volatile("tcgen05.wait::ld.sync.aligned;" ::: "memory");
#else
#pragma unroll
    for (int i = 0; i < 32; i++) r[i] = 0;
#endif
}
__device__ __forceinline__ void mbar_init(uint32_t a) {
    asm volatile("mbarrier.init.shared.b64 [%0], %1;" :: "r"(a), "r"(1u) : "memory");
}
__device__ __forceinline__ void mbar_wait(uint32_t a, int parity) {
    asm volatile(
        "{\n\t.reg .pred P;\n"
        "W_%=:\n\t"
        "mbarrier.try_wait.parity.acquire.cta.shared::cta.b64 P, [%0], %1, 0x989680;\n\t"
        "@P bra.uni D_%=;\n\t"
        "bra.uni W_%=;\n"
        "D_%=:\n\t}"
        :: "r"(a), "r"(parity) : "memory");
}

// ---------------- TC tile loader (SW128) ----------------
__device__ __forceinline__ void load_tiles(const __nv_bfloat16* __restrict__ A, int lda,
                                           const __nv_bfloat16* __restrict__ B, int ldb,
                                           int k0, char* da, char* db, int t) {
#pragma unroll
    for (int i = 0; i < 8; i++) {
        int idx = t + i * 128;
        int r = idx >> 3, cc = idx & 7;
        float4 v = *(const float4*)(A + (size_t)r * lda + k0 + cc * 8);
        uint32_t off = r * 128 + cc * 16;
        *(float4*)(da + (off ^ ((off >> 3) & 0x70))) = v;
    }
#pragma unroll
    for (int i = 0; i < 16; i++) {
        int idx = t + i * 128;
        int r = idx >> 3, cc = idx & 7;
        float4 v = *(const float4*)(B + (size_t)r * ldb + k0 + cc * 8);
        uint32_t off = r * 128 + cc * 16;
        *(float4*)(db + (off ^ ((off >> 3) & 0x70))) = v;
    }
}

__device__ __forceinline__ void seg_sel(const __nv_bfloat16* Ah, const __nv_bfloat16* Al,
                                        const __nv_bfloat16* Bh, const __nv_bfloat16* Bl,
                                        int ck, int nseg,
                                        const __nv_bfloat16*& Ap, const __nv_bfloat16*& Bp, int& k0) {
    int seg = (ck >= nseg) + (ck >= 2 * nseg);
    Ap = (seg == 1) ? Al : Ah;
    Bp = (seg == 2) ? Bl : Bh;
    k0 = (ck - seg * nseg) * 64;
}

// D[128x256] = Ah*Bh^T + Al*Bh^T + Ah*Bl^T
__device__ __forceinline__ uint32_t run_gemm3(const __nv_bfloat16* __restrict__ Ah,
                                              const __nv_bfloat16* __restrict__ Al,
                                              const __nv_bfloat16* __restrict__ Bh,
                                              const __nv_bfloat16* __restrict__ Bl,
                                              int lda, int ldb, int nseg, char* smem) {
    const int t = threadIdx.x;
    const int nch = 3 * nseg;
    uint32_t sb = smem_u32(smem);
    if (t < 32) tc_alloc(sb + SM_PTR);
    if (t == 0) { mbar_init(sb + SM_MBAR0); mbar_init(sb + SM_MBAR1); }
    __syncthreads();
    uint32_t tmem;
    asm volatile("ld.shared.b32 %0, [%1];" : "=r"(tmem) : "r"(sb + SM_PTR));

    int ph0 = 0, ph1 = 0;
    load_tiles(Ah, lda, Bh, ldb, 0, smem + SM_A, smem + SM_B, t);
    __syncthreads();

    for (int ck = 0; ck < nch; ck++) {
        const int pb = ck & 1;
        if (t < 32) {
            asm volatile("fence.proxy.async.shared::cta;" ::: "memory");
            if (elect1()) {
                uint64_t ad = make_desc(sb + SM_A + pb * 16384);
                uint64_t bd = make_desc(sb + SM_B + pb * 32768);
#pragma unroll
                for (int s = 0; s < 4; s++)
                    mma_bf16(tmem, ad + 2 * s, bd + 2 * s, (ck | s) != 0);
                tc_commit(sb + SM_MBAR0 + pb * 8);
            }
        }
        if (ck + 1 < nch) {
            const int nb2 = pb ^ 1;
            if (ck >= 1) {
                if (nb2 == 0) { mbar_wait(sb + SM_MBAR0, ph0); ph0 ^= 1; }
                else          { mbar_wait(sb + SM_MBAR1, ph1); ph1 ^= 1; }
            }
            const __nv_bfloat16 *Ap, *Bp;
            int k0;
            seg_sel(Ah, Al, Bh, Bl, ck + 1, nseg, Ap, Bp, k0);
            load_tiles(Ap, lda, Bp, ldb, k0,
                       smem + SM_A + nb2 * 16384, smem + SM_B + nb2 * 32768, t);
        }
        __syncthreads();
    }
    if (((nch - 1) & 1) == 0) mbar_wait(sb + SM_MBAR0, ph0);
    else                      mbar_wait(sb + SM_MBAR1, ph1);
    tc_fence_after();
    return tmem;
}

__device__ __forceinline__ void gemm_dealloc(uint32_t tmem) {
    __syncthreads();
    if (threadIdx.x < 32) tc_dealloc(tmem);
}

// ---------------- 1) BN stats ----------------
__global__ void __launch_bounds__(256) bn_stats(const float* __restrict__ x,
                                                const float* __restrict__ gamma,
                                                const float* __restrict__ beta) {
    int c = blockIdx.x, t = threadIdx.x;
    float s = 0.f, sq = 0.f;
    for (int b = 0; b < BB; b++) {
        const float* p = x + ((size_t)b * C + c) * L;
        for (int l = t; l < L; l += 256) { float v = p[l]; s += v; sq += v * v; }
    }
    __shared__ float sh0[256], sh1[256];
    sh0[t] = s; sh1[t] = sq;
    __syncthreads();
    for (int o = 128; o > 0; o >>= 1) {
        if (t < o) { sh0[t] += sh0[t + o]; sh1[t] += sh1[t + o]; }
        __syncthreads();
    }
    if (t == 0) {
        const float inv_n = 1.f / (float)(BB * L);
        float mean = sh0[0] * inv_n;
        float var  = sh1[0] * inv_n - mean * mean;
        float rs   = rsqrtf(var + EPSV);
        float sc   = gamma[c] * rs;
        g_scale[c] = sc;
        g_shift[c] = beta[c] - mean * sc;
    }
}

// ---------------- 2) split RAW weights (BN applied ONLY to x, not weights) ----------------
__global__ void __launch_bounds__(256) split_weights(const float* __restrict__ wq,
                                                     const float* __restrict__ wk,
                                                     const float* __restrict__ wv,
                                                     const float* __restrict__ wp) {
    int mat = blockIdx.y;
    const float* w = (mat == 0) ? wq : ((mat == 1) ? wk : ((mat == 2) ? wv : wp));
    size_t i = ((size_t)blockIdx.x * 256 + threadIdx.x) * 2;  // i < C*C
    float2 v = *(const float2*)(w + i);
    wsplit2(g_wbh + (size_t)mat * C * C, g_wbl + (size_t)mat * C * C, i, v.x, v.y);
}

// ---------------- 3) normalize + transpose + split x -> xth/xtl rows l ----------------
__global__ void __launch_bounds__(256) prep_xsplit(const float* __restrict__ x) {
    __shared__ float tile[32][33];
    int bi = blockIdx.z;
    int l0 = blockIdx.x * 32, c0 = blockIdx.y * 32;
    int tx = threadIdx.x, ty = threadIdx.y;
#pragma unroll
    for (int j = 0; j < 4; j++) {
        int c = c0 + ty + j * 8;
        float v = x[((size_t)bi * C + c) * L + l0 + tx];
        tile[ty + j * 8][tx] = v * g_scale[c] + g_shift[c];
    }
    __syncthreads();
#pragma unroll
    for (int j = 0; j < 4; j++) {
        int l = l0 + ty + j * 8;
        float v = tile[tx][ty + j * 8];
        uint16_t hb, lb;
        split_bf16(v, hb, lb);
        size_t idx = ((size_t)bi * L + l) * C + c0 + tx;
        *(uint16_t*)&g_xth[idx] = hb;
        *(uint16_t*)&g_xtl[idx] = lb;
    }
}

// ---------------- 4) q/k TC projection: D[l,o] fp32 + raw bias ----------------
__global__ void __launch_bounds__(128) qk_gemm_tc(const float* __restrict__ bq,
                                                  const float* __restrict__ bk) {
    extern __shared__ char smem[];
    int bi = blockIdx.y >> 1, mat = blockIdx.y & 1;
    int l0 = blockIdx.x * 128;
    size_t arow = ((size_t)bi * L + l0) * C;
    uint32_t tmem = run_gemm3(g_xth + arow, g_xtl + arow,
                              g_wbh + (size_t)mat * C * C, g_wbl + (size_t)mat * C * C, C, C, 4, smem);

    int t = threadIdx.x;
    float* dst = (mat ? g_kT : g_qT) + ((size_t)bi * L + l0 + t) * C;
    const float* bias = mat ? bk : bq;
    for (int nb = 0; nb < 8; nb++) {
        uint32_t r[32];
        ldtm32(r, tmem + nb * 32);
#pragma unroll
        for (int j = 0; j < 8; j++) {
            int n = nb * 32 + 4 * j;
            float4 v;
            v.x = __uint_as_float(r[4 * j + 0]) + bias[n + 0];
            v.y = __uint_as_float(r[4 * j + 1]) + bias[n + 1];
            v.z = __uint_as_float(r[4 * j + 2]) + bias[n + 2];
            v.w = __uint_as_float(r[4 * j + 3]) + bias[n + 3];
            *(float4*)(dst + n) = v;
        }
    }
    gemm_dealloc(tmem);
}

// ---------------- 5) split q/k (elementwise) ----------------
__global__ void __launch_bounds__(256) split_qk() {
    int mat = blockIdx.y;
    size_t i = ((size_t)blockIdx.x * 256 + threadIdx.x) * 2;
    const float* src = mat ? g_kT : g_qT;
    float2 v = *(const float2*)(src + i);
    wsplit2(mat ? g_kh : g_qh, mat ? g_kl : g_ql, i, v.x, v.y);
}

// ---------------- 6) v TC projection: D[o,l] fp32 + raw bias -> g_vf [c][l] ----------------
__global__ void __launch_bounds__(128) v_gemm_tc(const float* __restrict__ bv) {
    extern __shared__ char smem[];
    int bi = blockIdx.z, o0 = blockIdx.y * 128, l0 = blockIdx.x * 256;
    size_t brow = ((size_t)bi * L + l0) * C;
    uint32_t tmem = run_gemm3(g_wbh + 2 * C * C + o0 * C, g_wbl + 2 * C * C + o0 * C,
                              g_xth + brow, g_xtl + brow, C, C, 4, smem);

    int t = threadIdx.x;
    float bias = bv[o0 + t];
    float* dst = g_vf + ((size_t)bi * C + o0 + t) * L + l0;
    for (int nb = 0; nb < 8; nb++) {
        uint32_t r[32];
        ldtm32(r, tmem + nb * 32);
#pragma unroll
        for (int j = 0; j < 8; j++) {
            float4 v;
            v.x = __uint_as_float(r[4 * j + 0]) + bias;
            v.y = __uint_as_float(r[4 * j + 1]) + bias;
            v.z = __uint_as_float(r[4 * j + 2]) + bias;
            v.w = __uint_as_float(r[4 * j + 3]) + bias;
            *(float4*)(dst + nb * 32 + 4 * j) = v;
        }
    }
    gemm_dealloc(tmem);
}

// ---------------- 7) split v (elementwise) ----------------
__global__ void __launch_bounds__(256) split_v() {
    size_t i = ((size_t)blockIdx.x * 256 + threadIdx.x) * 2;
    float2 v = *(const float2*)(g_vf + i);
    wsplit2(g_vh, g_vl, i, v.x, v.y);
}

// ---------------- 8) scores TC ----------------
__global__ void __launch_bounds__(128) scores_gemm_tc() {
    extern __shared__ char smem[];
    int bi = blockIdx.z, i0 = blockIdx.y * 128, j0 = blockIdx.x * 256;
    size_t arow = ((size_t)bi * L + i0) * C;
    size_t brow = ((size_t)bi * L + j0) * C;
    uint32_t tmem = run_gemm3(g_qh + arow, g_ql + arow, g_kh + brow, g_kl + brow, C, C, 4, smem);

    int t = threadIdx.x;
    float* dst = g_s + ((size_t)bi * L + i0 + t) * L + j0;
    const float scale = 0.0625f;
    for (int nb = 0; nb < 8; nb++) {
        uint32_t r[32];
        ldtm32(r, tmem + nb * 32);
#pragma unroll
        for (int j = 0; j < 8; j++) {
            float4 v;
            v.x = __uint_as_float(r[4 * j + 0]) * scale;
            v.y = __uint_as_float(r[4 * j + 1]) * scale;
            v.z = __uint_as_float(r[4 * j + 2]) * scale;
            v.w = __uint_as_float(r[4 * j + 3]) * scale;
            *(float4*)(dst + nb * 32 + 4 * j) = v;
        }
    }
    gemm_dealloc(tmem);
}

// ---------------- 9) softmax rows -> ph/pl ----------------
__global__ void __launch_bounds__(256) softmax_rows() {
    size_t row = blockIdx.x;
    const float* p = g_s + row * (size_t)L;
    const int t = threadIdx.x;
    float2 r[8];
    float mx = -1e30f;
#pragma unroll
    for (int i = 0; i < 8; i++) {
        r[i] = *(const float2*)(p + i * 512 + t * 2);
        mx = fmaxf(mx, fmaxf(r[i].x, r[i].y));
    }
#pragma unroll
    for (int o = 16; o; o >>= 1) mx = fmaxf(mx, __shfl_xor_sync(0xffffffffu, mx, o));
    __shared__ float sm[8];
    if ((t & 31) == 0) sm[t >> 5] = mx;
    __syncthreads();
    float bm = sm[0];
#pragma unroll
    for (int i = 1; i < 8; i++) bm = fmaxf(bm, sm[i]);
    float s = 0.f;
#pragma unroll
    for (int i = 0; i < 8; i++) {
        r[i].x = __expf(r[i].x - bm);
        r[i].y = __expf(r[i].y - bm);
        s += r[i].x + r[i].y;
    }
#pragma unroll
    for (int o = 16; o; o >>= 1) s += __shfl_xor_sync(0xffffffffu, s, o);
    __syncthreads();
    if ((t & 31) == 0) sm[t >> 5] = s;
    __syncthreads();
    float tot = 0.f;
#pragma unroll
    for (int i = 0; i < 8; i++) tot += sm[i];
    float inv = 1.f / tot;
    size_t base = row * (size_t)L;
#pragma unroll
    for (int i = 0; i < 8; i++)
        wsplit2(g_ph, g_pl, base + i * 512 + t * 2, r[i].x * inv, r[i].y * inv);
}

// ---------------- 10) AV TC: writes fp32 h[c][l] ----------------
__global__ void __launch_bounds__(128) av_gemm_tc() {
    extern __shared__ char smem[];
    int bi = blockIdx.y, i0 = blockIdx.x * 128;
    size_t arow = ((size_t)bi * L + i0) * L;
    size_t brow = (size_t)bi * C * L;
    uint32_t tmem = run_gemm3(g_ph + arow, g_pl + arow, g_vh + brow, g_vl + brow, L, L, 64, smem);

    int t = threadIdx.x;
    float* hb = g_h + (size_t)bi * C * L;
    for (int nb = 0; nb < 8; nb++) {
        uint32_t r[32];
        ldtm32(r, tmem + nb * 32);
#pragma unroll
        for (int j = 0; j < 32; j++) {
            int c = nb * 32 + j;
            hb[(size_t)c * L + i0 + t] = __uint_as_float(r[j]);
        }
    }
    gemm_dealloc(tmem);
}

// ---------------- 11) transpose + split h -> hth/htl rows l ----------------
__global__ void __launch_bounds__(256) transpose_split_h() {
    __shared__ float tile[32][33];
    int bi = blockIdx.z;
    int l0 = blockIdx.x * 32, c0 = blockIdx.y * 32;
    int tx = threadIdx.x, ty = threadIdx.y;
    const float* src = g_h + (size_t)bi * C * L;
#pragma unroll
    for (int j = 0; j < 4; j++)
        tile[ty + j * 8][tx] = src[(size_t)(c0 + ty + j * 8) * L + l0 + tx];
    __syncthreads();
#pragma unroll
    for (int j = 0; j < 4; j++) {
        int l = l0 + ty + j * 8;
        float v = tile[tx][ty + j * 8];
        uint16_t hb, lb;
        split_bf16(v, hb, lb);
        size_t idx = ((size_t)bi * L + l) * C + c0 + tx;
        *(uint16_t*)&g_hth[idx] = hb;
        *(uint16_t*)&g_htl[idx] = lb;
    }
}

// ---------------- 12) proj TC: D[o,l] + raw bias + residual -> out ----------------
__global__ void __launch_bounds__(128) proj_gemm_tc(const float* __restrict__ x,
                                                    const float* __restrict__ bp,
                                                    float* __restrict__ out) {
    extern __shared__ char smem[];
    int bi = blockIdx.z, o0 = blockIdx.y * 128, l0 = blockIdx.x * 256;
    size_t brow = ((size_t)bi * L + l0) * C;
    uint32_t tmem = run_gemm3(g_wbh + 3 * C * C + o0 * C, g_wbl + 3 * C * C + o0 * C,
                              g_hth + brow, g_htl + brow, C, C, 4, smem);

    int t = threadIdx.x;
    float bias = bp[o0 + t];
    size_t base = ((size_t)bi * C + o0 + t) * L + l0;
    for (int nb = 0; nb < 8; nb++) {
        uint32_t r[32];
        ldtm32(r, tmem + nb * 32);
#pragma unroll
        for (int j = 0; j < 8; j++) {
            float4 xr = *(const float4*)(x + base + nb * 32 + 4 * j);
            float4 v;
            v.x = __uint_as_float(r[4 * j + 0]) + bias + xr.x;
            v.y = __uint_as_float(r[4 * j + 1]) + bias + xr.y;
            v.z = __uint_as_float(r[4 * j + 2]) + bias + xr.z;
            v.w = __uint_as_float(r[4 * j + 3]) + bias + xr.w;
            *(float4*)(out + base + nb * 32 + 4 * j) = v;
        }
    }
    gemm_dealloc(tmem);
}

// ---------------- launch ----------------
extern "C" void kernel_launch(void* const* d_in, const int* in_sizes, int n_in,
                              void* d_out, int out_size) {
    const float* x     = (const float*)d_in[0];
    const float* gamma = (const float*)d_in[1];
    const float* beta  = (const float*)d_in[2];
    const float* wq    = (const float*)d_in[3];
    const float* bq    = (const float*)d_in[4];
    const float* wk    = (const float*)d_in[5];
    const float* bk    = (const float*)d_in[6];
    const float* wv    = (const float*)d_in[7];
    const float* bv    = (const float*)d_in[8];
    const float* wp    = (const float*)d_in[9];
    const float* bp    = (const float*)d_in[10];
    float* out = (float*)d_out;

    cudaFuncSetAttribute(qk_gemm_tc,     cudaFuncAttributeMaxDynamicSharedMemorySize, SMEMSZ);
    cudaFuncSetAttribute(v_gemm_tc,      cudaFuncAttributeMaxDynamicSharedMemorySize, SMEMSZ);
    cudaFuncSetAttribute(scores_gemm_tc, cudaFuncAttributeMaxDynamicSharedMemorySize, SMEMSZ);
    cudaFuncSetAttribute(av_gemm_tc,     cudaFuncAttributeMaxDynamicSharedMemorySize, SMEMSZ);
    cudaFuncSetAttribute(proj_gemm_tc,   cudaFuncAttributeMaxDynamicSharedMemorySize, SMEMSZ);

    bn_stats<<<C, 256>>>(x, gamma, beta);
    split_weights<<<dim3((C * C / 2) / 256, 4), 256>>>(wq, wk, wv, wp);
    prep_xsplit<<<dim3(L / 32, C / 32, BB), dim3(32, 8)>>>(x);
    qk_gemm_tc<<<dim3(L / 128, BB * 2), 128, SMEMSZ>>>(bq, bk);
    split_qk<<<dim3((int)(((size_t)BB * L * C / 2) / 256), 2), 256>>>();
    v_gemm_tc<<<dim3(L / 256, C / 128, BB), 128, SMEMSZ>>>(bv);
    split_v<<<(int)(((size_t)BB * C * L / 2) / 256), 256>>>();
    scores_gemm_tc<<<dim3(L / 256, L / 128, BB), 128, SMEMSZ>>>();
    softmax_rows<<<BB * L, 256>>>();
    av_gemm_tc<<<dim3(L / 128, BB), 128, SMEMSZ>>>();
    transpose_split_h<<<dim3(L / 32, C / 32, BB), dim3(32, 8)>>>();
    proj_gemm_tc<<<dim3(L / 256, C / 128, BB), 128, SMEMSZ>>>(x, bp, out);
}

// round 9
// speedup vs baseline: 4.5296x; 1.9383x over previous
#include <cuda_runtime.h>
#include <cuda_bf16.h>
#include <cstdint>

#define BB 4
#define C 256
#define L 4096
#define EPSV 1e-5f

#if defined(__CUDA_ARCH_FEAT_SM103_ALL) || defined(__CUDA_ARCH_FEAT_SM100_ALL) || defined(__CUDA_ARCH_FAMILY_SPECIFIC__)
#define TC_OK 1
#else
#define TC_OK 0
#endif

// ---------------- device scratch ----------------
__device__ float g_scale[C];
__device__ float g_shift[C];
__device__ __align__(16) __nv_bfloat16 g_wbh[4 * C * C], g_wbl[4 * C * C];   // RAW weights, split
__device__ __align__(16) __nv_bfloat16 g_xth[(size_t)BB * L * C], g_xtl[(size_t)BB * L * C];
__device__ float g_qT[(size_t)BB * L * C];
__device__ float g_kT[(size_t)BB * L * C];
__device__ float g_vf[(size_t)BB * C * L];
__device__ float g_h[(size_t)BB * C * L];
__device__ float g_s[(size_t)BB * L * L];
__device__ __align__(16) __nv_bfloat16 g_qh[(size_t)BB * L * C], g_ql[(size_t)BB * L * C];
__device__ __align__(16) __nv_bfloat16 g_kh[(size_t)BB * L * C], g_kl[(size_t)BB * L * C];
__device__ __align__(16) __nv_bfloat16 g_vh[(size_t)BB * C * L], g_vl[(size_t)BB * C * L];
__device__ __align__(16) __nv_bfloat16 g_ph[(size_t)BB * L * L], g_pl[(size_t)BB * L * L];
__device__ __align__(16) __nv_bfloat16 g_hth[(size_t)BB * L * C], g_htl[(size_t)BB * L * C];

// ---------------- SMEM layout ----------------
#define SM_PTR   0
#define SM_MBAR0 8
#define SM_MBAR1 16
#define SM_A     1024
#define SM_B     (1024 + 32768)
#define SMEMSZ   (1024 + 32768 + 65536)

#define IDESC_BF16 0x8400490u

// ---------------- fold-proof bf16 hi/lo split ----------------
__device__ __forceinline__ void split_bf16(float v, uint16_t& hb, uint16_t& lb) {
    float hf, r;
    asm("cvt.rn.bf16.f32 %0, %1;" : "=h"(hb) : "f"(v));
    asm("cvt.f32.bf16 %0, %1;"    : "=f"(hf) : "h"(hb));
    asm("sub.rn.f32 %0, %1, %2;"  : "=f"(r)  : "f"(v), "f"(hf));
    asm("cvt.rn.bf16.f32 %0, %1;" : "=h"(lb) : "f"(r));
}
__device__ __forceinline__ void wsplit2(__nv_bfloat16* h, __nv_bfloat16* l, size_t idx,
                                        float a, float b) {
    uint16_t ha, la, hbb, lbb;
    split_bf16(a, ha, la);
    split_bf16(b, hbb, lbb);
    uint32_t hp = (uint32_t)ha | ((uint32_t)hbb << 16);
    uint32_t lp = (uint32_t)la | ((uint32_t)lbb << 16);
    *(uint32_t*)((char*)h + idx * 2) = hp;
    *(uint32_t*)((char*)l + idx * 2) = lp;
}

// ---------------- tcgen05 helpers ----------------
__device__ __forceinline__ uint32_t smem_u32(const void* p) {
    uint32_t a;
    asm("{ .reg .u64 t; cvta.to.shared.u64 t, %1; cvt.u32.u64 %0, t; }" : "=r"(a) : "l"(p));
    return a;
}
__device__ __forceinline__ uint32_t elect1() {
    uint32_t p;
    asm volatile("{\n\t.reg .pred p;\n\telect.sync _|p, 0xFFFFFFFF;\n\tselp.b32 %0, 1, 0, p;\n\t}" : "=r"(p));
    return p;
}
__device__ __forceinline__ uint64_t make_desc(uint32_t addr) {
    return (2ULL << 61) | (1ULL << 46) | (64ULL << 32) | (1ULL << 16) |
           ((uint64_t)(addr >> 4) & 0x3FFF);
}
__device__ __forceinline__ void tc_alloc(uint32_t sptr) {
#if TC_OK
    asm volatile("tcgen05.alloc.cta_group::1.sync.aligned.shared::cta.b32 [%0], %1;"
                 :: "r"(sptr), "r"(256u) : "memory");
    asm volatile("tcgen05.relinquish_alloc_permit.cta_group::1.sync.aligned;");
#endif
}
__device__ __forceinline__ void tc_dealloc(uint32_t tmem) {
#if TC_OK
    asm volatile("tcgen05.dealloc.cta_group::1.sync.aligned.b32 %0, %1;" :: "r"(tmem), "r"(256u));
#endif
}
__device__ __forceinline__ void mma_bf16(uint32_t d, uint64_t ad, uint64_t bd, bool acc) {
#if TC_OK
    uint32_t e = acc ? 1u : 0u;
    asm volatile(
        "{\n\t.reg .pred p;\n\tsetp.ne.u32 p, %4, 0;\n\t"
        "tcgen05.mma.cta_group::1.kind::f16 [%0], %1, %2, %3, {%5, %5, %5, %5}, p;\n\t}"
        :: "r"(d), "l"(ad), "l"(bd), "r"(IDESC_BF16), "r"(e), "r"(0u) : "memory");
#endif
}
__device__ __forceinline__ void tc_commit(uint32_t mbar) {
#if TC_OK
    asm volatile("tcgen05.commit.cta_group::1.mbarrier::arrive::one.shared::cluster.b64 [%0];"
                 :: "r"(mbar) : "memory");
#endif
}
__device__ __forceinline__ void tc_fence_after() {
#if TC_OK
    asm volatile("tcgen05.fence::after_thread_sync;" ::: "memory");
#endif
}
__device__ __forceinline__ void ldtm32(uint32_t* r, uint32_t addr) {
#if TC_OK
    asm volatile(
        "tcgen05.ld.sync.aligned.32x32b.x32.b32 "
        "{%0, %1, %2, %3, %4, %5, %6, %7, "
        " %8, %9, %10, %11, %12, %13, %14, %15, "
        " %16, %17, %18, %19, %20, %21, %22, %23, "
        " %24, %25, %26, %27, %28, %29, %30, %31}, [%32];"
        : "=r"(r[0]),  "=r"(r[1]),  "=r"(r[2]),  "=r"(r[3]),
          "=r"(r[4]),  "=r"(r[5]),  "=r"(r[6]),  "=r"(r[7]),
          "=r"(r[8]),  "=r"(r[9]),  "=r"(r[10]), "=r"(r[11]),
          "=r"(r[12]), "=r"(r[13]), "=r"(r[14]), "=r"(r[15]),
          "=r"(r[16]), "=r"(r[17]), "=r"(r[18]), "=r"(r[19]),
          "=r"(r[20]), "=r"(r[21]), "=r"(r[22]), "=r"(r[23]),
          "=r"(r[24]), "=r"(r[25]), "=r"(r[26]), "=r"(r[27]),
          "=r"(r[28]), "=r"(r[29]), "=r"(r[30]), "=r"(r[31])
        : "r"(addr));
    asm volatile("tcgen05.wait::ld.sync.aligned;" ::: "memory");
#else
#pragma unroll
    for (int i = 0; i < 32; i++) r[i] = 0;
#endif
}
__device__ __forceinline__ void mbar_init(uint32_t a) {
    asm volatile("mbarrier.init.shared.b64 [%0], %1;" :: "r"(a), "r"(1u) : "memory");
}
__device__ __forceinline__ void mbar_wait(uint32_t a, int parity) {
    asm volatile(
        "{\n\t.reg .pred P;\n"
        "W_%=:\n\t"
        "mbarrier.try_wait.parity.acquire.cta.shared::cta.b64 P, [%0], %1, 0x989680;\n\t"
        "@P bra.uni D_%=;\n\t"
        "bra.uni W_%=;\n"
        "D_%=:\n\t}"
        :: "r"(a), "r"(parity) : "memory");
}

// ---------------- register-prefetch tile load/store (256 threads) ----------------
__device__ __forceinline__ void ldg_tiles(const __nv_bfloat16* __restrict__ A, int lda,
                                          const __nv_bfloat16* __restrict__ B, int ldb,
                                          int k0, int t, float4* ra, float4* rb) {
#pragma unroll
    for (int i = 0; i < 4; i++) {
        int idx = t + i * 256;
        int r = idx >> 3, cc = idx & 7;
        ra[i] = *(const float4*)(A + (size_t)r * lda + k0 + cc * 8);
    }
#pragma unroll
    for (int i = 0; i < 8; i++) {
        int idx = t + i * 256;
        int r = idx >> 3, cc = idx & 7;
        rb[i] = *(const float4*)(B + (size_t)r * ldb + k0 + cc * 8);
    }
}
__device__ __forceinline__ void sts_tiles(char* da, char* db, int t,
                                          const float4* ra, const float4* rb) {
#pragma unroll
    for (int i = 0; i < 4; i++) {
        int idx = t + i * 256;
        int r = idx >> 3, cc = idx & 7;
        uint32_t off = r * 128 + cc * 16;
        *(float4*)(da + (off ^ ((off >> 3) & 0x70))) = ra[i];
    }
#pragma unroll
    for (int i = 0; i < 8; i++) {
        int idx = t + i * 256;
        int r = idx >> 3, cc = idx & 7;
        uint32_t off = r * 128 + cc * 16;
        *(float4*)(db + (off ^ ((off >> 3) & 0x70))) = rb[i];
    }
}

__device__ __forceinline__ void seg_sel(const __nv_bfloat16* Ah, const __nv_bfloat16* Al,
                                        const __nv_bfloat16* Bh, const __nv_bfloat16* Bl,
                                        int ck, int nseg,
                                        const __nv_bfloat16*& Ap, const __nv_bfloat16*& Bp, int& k0) {
    int seg = (ck >= nseg) + (ck >= 2 * nseg);
    Ap = (seg == 1) ? Al : Ah;
    Bp = (seg == 2) ? Bl : Bh;
    k0 = (ck - seg * nseg) * 64;
}

// D[128x256] = Ah*Bh^T + Al*Bh^T + Ah*Bl^T   (256 threads, reg-prefetch pipeline)
__device__ __forceinline__ uint32_t run_gemm3(const __nv_bfloat16* __restrict__ Ah,
                                              const __nv_bfloat16* __restrict__ Al,
                                              const __nv_bfloat16* __restrict__ Bh,
                                              const __nv_bfloat16* __restrict__ Bl,
                                              int lda, int ldb, int nseg, char* smem) {
    const int t = threadIdx.x;
    const int nch = 3 * nseg;
    uint32_t sb = smem_u32(smem);
    if (t < 32) tc_alloc(sb + SM_PTR);
    if (t == 0) { mbar_init(sb + SM_MBAR0); mbar_init(sb + SM_MBAR1); }
    __syncthreads();
    uint32_t tmem;
    asm volatile("ld.shared.b32 %0, [%1];" : "=r"(tmem) : "r"(sb + SM_PTR));

    int ph0 = 0, ph1 = 0;
    float4 ra[4], rb[8];
    ldg_tiles(Ah, lda, Bh, ldb, 0, t, ra, rb);
    sts_tiles(smem + SM_A, smem + SM_B, t, ra, rb);
    __syncthreads();

    for (int ck = 0; ck < nch; ck++) {
        const int pb = ck & 1;
        if (t < 32) {
            asm volatile("fence.proxy.async.shared::cta;" ::: "memory");
            if (elect1()) {
                uint64_t ad = make_desc(sb + SM_A + pb * 16384);
                uint64_t bd = make_desc(sb + SM_B + pb * 32768);
#pragma unroll
                for (int s = 0; s < 4; s++)
                    mma_bf16(tmem, ad + 2 * s, bd + 2 * s, (ck | s) != 0);
                tc_commit(sb + SM_MBAR0 + pb * 8);
            }
        }
        if (ck + 1 < nch) {
            const int nb2 = pb ^ 1;
            const __nv_bfloat16 *Ap, *Bp;
            int k0;
            seg_sel(Ah, Al, Bh, Bl, ck + 1, nseg, Ap, Bp, k0);
            ldg_tiles(Ap, lda, Bp, ldb, k0, t, ra, rb);     // LDG latency overlaps MMA wait
            if (ck >= 1) {
                if (nb2 == 0) { mbar_wait(sb + SM_MBAR0, ph0); ph0 ^= 1; }
                else          { mbar_wait(sb + SM_MBAR1, ph1); ph1 ^= 1; }
            }
            sts_tiles(smem + SM_A + nb2 * 16384, smem + SM_B + nb2 * 32768, t, ra, rb);
        }
        __syncthreads();
    }
    if (((nch - 1) & 1) == 0) mbar_wait(sb + SM_MBAR0, ph0);
    else                      mbar_wait(sb + SM_MBAR1, ph1);
    tc_fence_after();
    return tmem;
}

__device__ __forceinline__ void gemm_dealloc(uint32_t tmem) {
    __syncthreads();
    if (threadIdx.x < 32) tc_dealloc(tmem);
}

// ---------------- 1) BN stats ----------------
__global__ void __launch_bounds__(256) bn_stats(const float* __restrict__ x,
                                                const float* __restrict__ gamma,
                                                const float* __restrict__ beta) {
    int c = blockIdx.x, t = threadIdx.x;
    float s = 0.f, sq = 0.f;
    for (int b = 0; b < BB; b++) {
        const float* p = x + ((size_t)b * C + c) * L;
        for (int l = t; l < L; l += 256) { float v = p[l]; s += v; sq += v * v; }
    }
    __shared__ float sh0[256], sh1[256];
    sh0[t] = s; sh1[t] = sq;
    __syncthreads();
    for (int o = 128; o > 0; o >>= 1) {
        if (t < o) { sh0[t] += sh0[t + o]; sh1[t] += sh1[t + o]; }
        __syncthreads();
    }
    if (t == 0) {
        const float inv_n = 1.f / (float)(BB * L);
        float mean = sh0[0] * inv_n;
        float var  = sh1[0] * inv_n - mean * mean;
        float rs   = rsqrtf(var + EPSV);
        float sc   = gamma[c] * rs;
        g_scale[c] = sc;
        g_shift[c] = beta[c] - mean * sc;
    }
}

// ---------------- 2) split RAW weights ----------------
__global__ void __launch_bounds__(256) split_weights(const float* __restrict__ wq,
                                                     const float* __restrict__ wk,
                                                     const float* __restrict__ wv,
                                                     const float* __restrict__ wp) {
    int mat = blockIdx.y;
    const float* w = (mat == 0) ? wq : ((mat == 1) ? wk : ((mat == 2) ? wv : wp));
    size_t i = ((size_t)blockIdx.x * 256 + threadIdx.x) * 2;
    float2 v = *(const float2*)(w + i);
    wsplit2(g_wbh + (size_t)mat * C * C, g_wbl + (size_t)mat * C * C, i, v.x, v.y);
}

// ---------------- 3) normalize + transpose + split x ----------------
__global__ void __launch_bounds__(256) prep_xsplit(const float* __restrict__ x) {
    __shared__ float tile[32][33];
    int bi = blockIdx.z;
    int l0 = blockIdx.x * 32, c0 = blockIdx.y * 32;
    int tx = threadIdx.x, ty = threadIdx.y;
#pragma unroll
    for (int j = 0; j < 4; j++) {
        int c = c0 + ty + j * 8;
        float v = x[((size_t)bi * C + c) * L + l0 + tx];
        tile[ty + j * 8][tx] = v * g_scale[c] + g_shift[c];
    }
    __syncthreads();
#pragma unroll
    for (int j = 0; j < 4; j++) {
        int l = l0 + ty + j * 8;
        float v = tile[tx][ty + j * 8];
        uint16_t hb, lb;
        split_bf16(v, hb, lb);
        size_t idx = ((size_t)bi * L + l) * C + c0 + tx;
        *(uint16_t*)&g_xth[idx] = hb;
        *(uint16_t*)&g_xtl[idx] = lb;
    }
}

// ---------------- 4) q/k TC projection (256 thr, 8-warp epilogue) ----------------
__global__ void __launch_bounds__(256) qk_gemm_tc(const float* __restrict__ bq,
                                                  const float* __restrict__ bk) {
    extern __shared__ char smem[];
    int bi = blockIdx.y >> 1, mat = blockIdx.y & 1;
    int l0 = blockIdx.x * 128;
    size_t arow = ((size_t)bi * L + l0) * C;
    uint32_t tmem = run_gemm3(g_xth + arow, g_xtl + arow,
                              g_wbh + (size_t)mat * C * C, g_wbl + (size_t)mat * C * C, C, C, 4, smem);

    int t = threadIdx.x, wt = t & 127, wg = t >> 7;
    float* dst = (mat ? g_kT : g_qT) + ((size_t)bi * L + l0 + wt) * C;
    const float* bias = mat ? bk : bq;
    for (int nbl = 0; nbl < 4; nbl++) {
        int nb = wg * 4 + nbl;
        uint32_t r[32];
        ldtm32(r, tmem + nb * 32);
#pragma unroll
        for (int j = 0; j < 8; j++) {
            int n = nb * 32 + 4 * j;
            float4 v;
            v.x = __uint_as_float(r[4 * j + 0]) + bias[n + 0];
            v.y = __uint_as_float(r[4 * j + 1]) + bias[n + 1];
            v.z = __uint_as_float(r[4 * j + 2]) + bias[n + 2];
            v.w = __uint_as_float(r[4 * j + 3]) + bias[n + 3];
            *(float4*)(dst + n) = v;
        }
    }
    gemm_dealloc(tmem);
}

// ---------------- 5) split q/k ----------------
__global__ void __launch_bounds__(256) split_qk() {
    int mat = blockIdx.y;
    size_t i = ((size_t)blockIdx.x * 256 + threadIdx.x) * 2;
    const float* src = mat ? g_kT : g_qT;
    float2 v = *(const float2*)(src + i);
    wsplit2(mat ? g_kh : g_qh, mat ? g_kl : g_ql, i, v.x, v.y);
}

// ---------------- 6) v TC projection ----------------
__global__ void __launch_bounds__(256) v_gemm_tc(const float* __restrict__ bv) {
    extern __shared__ char smem[];
    int bi = blockIdx.z, o0 = blockIdx.y * 128, l0 = blockIdx.x * 256;
    size_t brow = ((size_t)bi * L + l0) * C;
    uint32_t tmem = run_gemm3(g_wbh + 2 * C * C + o0 * C, g_wbl + 2 * C * C + o0 * C,
                              g_xth + brow, g_xtl + brow, C, C, 4, smem);

    int t = threadIdx.x, wt = t & 127, wg = t >> 7;
    float bias = bv[o0 + wt];
    float* dst = g_vf + ((size_t)bi * C + o0 + wt) * L + l0;
    for (int nbl = 0; nbl < 4; nbl++) {
        int nb = wg * 4 + nbl;
        uint32_t r[32];
        ldtm32(r, tmem + nb * 32);
#pragma unroll
        for (int j = 0; j < 8; j++) {
            float4 v;
            v.x = __uint_as_float(r[4 * j + 0]) + bias;
            v.y = __uint_as_float(r[4 * j + 1]) + bias;
            v.z = __uint_as_float(r[4 * j + 2]) + bias;
            v.w = __uint_as_float(r[4 * j + 3]) + bias;
            *(float4*)(dst + nb * 32 + 4 * j) = v;
        }
    }
    gemm_dealloc(tmem);
}

// ---------------- 7) split v ----------------
__global__ void __launch_bounds__(256) split_v() {
    size_t i = ((size_t)blockIdx.x * 256 + threadIdx.x) * 2;
    float2 v = *(const float2*)(g_vf + i);
    wsplit2(g_vh, g_vl, i, v.x, v.y);
}

// ---------------- 8) scores TC ----------------
__global__ void __launch_bounds__(256) scores_gemm_tc() {
    extern __shared__ char smem[];
    int bi = blockIdx.z, i0 = blockIdx.y * 128, j0 = blockIdx.x * 256;
    size_t arow = ((size_t)bi * L + i0) * C;
    size_t brow = ((size_t)bi * L + j0) * C;
    uint32_t tmem = run_gemm3(g_qh + arow, g_ql + arow, g_kh + brow, g_kl + brow, C, C, 4, smem);

    int t = threadIdx.x, wt = t & 127, wg = t >> 7;
    float* dst = g_s + ((size_t)bi * L + i0 + wt) * L + j0;
    const float scale = 0.0625f;
    for (int nbl = 0; nbl < 4; nbl++) {
        int nb = wg * 4 + nbl;
        uint32_t r[32];
        ldtm32(r, tmem + nb * 32);
#pragma unroll
        for (int j = 0; j < 8; j++) {
            float4 v;
            v.x = __uint_as_float(r[4 * j + 0]) * scale;
            v.y = __uint_as_float(r[4 * j + 1]) * scale;
            v.z = __uint_as_float(r[4 * j + 2]) * scale;
            v.w = __uint_as_float(r[4 * j + 3]) * scale;
            *(float4*)(dst + nb * 32 + 4 * j) = v;
        }
    }
    gemm_dealloc(tmem);
}

// ---------------- 9) softmax rows -> ph/pl ----------------
__global__ void __launch_bounds__(256) softmax_rows() {
    size_t row = blockIdx.x;
    const float* p = g_s + row * (size_t)L;
    const int t = threadIdx.x;
    float2 r[8];
    float mx = -1e30f;
#pragma unroll
    for (int i = 0; i < 8; i++) {
        r[i] = *(const float2*)(p + i * 512 + t * 2);
        mx = fmaxf(mx, fmaxf(r[i].x, r[i].y));
    }
#pragma unroll
    for (int o = 16; o; o >>= 1) mx = fmaxf(mx, __shfl_xor_sync(0xffffffffu, mx, o));
    __shared__ float sm[8];
    if ((t & 31) == 0) sm[t >> 5] = mx;
    __syncthreads();
    float bm = sm[0];
#pragma unroll
    for (int i = 1; i < 8; i++) bm = fmaxf(bm, sm[i]);
    float s = 0.f;
#pragma unroll
    for (int i = 0; i < 8; i++) {
        r[i].x = __expf(r[i].x - bm);
        r[i].y = __expf(r[i].y - bm);
        s += r[i].x + r[i].y;
    }
#pragma unroll
    for (int o = 16; o; o >>= 1) s += __shfl_xor_sync(0xffffffffu, s, o);
    __syncthreads();
    if ((t & 31) == 0) sm[t >> 5] = s;
    __syncthreads();
    float tot = 0.f;
#pragma unroll
    for (int i = 0; i < 8; i++) tot += sm[i];
    float inv = 1.f / tot;
    size_t base = row * (size_t)L;
#pragma unroll
    for (int i = 0; i < 8; i++)
        wsplit2(g_ph, g_pl, base + i * 512 + t * 2, r[i].x * inv, r[i].y * inv);
}

// ---------------- 10) AV TC: fp32 h[c][l] ----------------
__global__ void __launch_bounds__(256) av_gemm_tc() {
    extern __shared__ char smem[];
    int bi = blockIdx.y, i0 = blockIdx.x * 128;
    size_t arow = ((size_t)bi * L + i0) * L;
    size_t brow = (size_t)bi * C * L;
    uint32_t tmem = run_gemm3(g_ph + arow, g_pl + arow, g_vh + brow, g_vl + brow, L, L, 64, smem);

    int t = threadIdx.x, wt = t & 127, wg = t >> 7;
    float* hb = g_h + (size_t)bi * C * L;
    for (int nbl = 0; nbl < 4; nbl++) {
        int nb = wg * 4 + nbl;
        uint32_t r[32];
        ldtm32(r, tmem + nb * 32);
#pragma unroll
        for (int j = 0; j < 32; j++) {
            int c = nb * 32 + j;
            hb[(size_t)c * L + i0 + wt] = __uint_as_float(r[j]);
        }
    }
    gemm_dealloc(tmem);
}

// ---------------- 11) transpose + split h ----------------
__global__ void __launch_bounds__(256) transpose_split_h() {
    __shared__ float tile[32][33];
    int bi = blockIdx.z;
    int l0 = blockIdx.x * 32, c0 = blockIdx.y * 32;
    int tx = threadIdx.x, ty = threadIdx.y;
    const float* src = g_h + (size_t)bi * C * L;
#pragma unroll
    for (int j = 0; j < 4; j++)
        tile[ty + j * 8][tx] = src[(size_t)(c0 + ty + j * 8) * L + l0 + tx];
    __syncthreads();
#pragma unroll
    for (int j = 0; j < 4; j++) {
        int l = l0 + ty + j * 8;
        float v = tile[tx][ty + j * 8];
        uint16_t hb, lb;
        split_bf16(v, hb, lb);
        size_t idx = ((size_t)bi * L + l) * C + c0 + tx;
        *(uint16_t*)&g_hth[idx] = hb;
        *(uint16_t*)&g_htl[idx] = lb;
    }
}

// ---------------- 12) proj TC + bias + residual ----------------
__global__ void __launch_bounds__(256) proj_gemm_tc(const float* __restrict__ x,
                                                    const float* __restrict__ bp,
                                                    float* __restrict__ out) {
    extern __shared__ char smem[];
    int bi = blockIdx.z, o0 = blockIdx.y * 128, l0 = blockIdx.x * 256;
    size_t brow = ((size_t)bi * L + l0) * C;
    uint32_t tmem = run_gemm3(g_wbh + 3 * C * C + o0 * C, g_wbl + 3 * C * C + o0 * C,
                              g_hth + brow, g_htl + brow, C, C, 4, smem);

    int t = threadIdx.x, wt = t & 127, wg = t >> 7;
    float bias = bp[o0 + wt];
    size_t base = ((size_t)bi * C + o0 + wt) * L + l0;
    for (int nbl = 0; nbl < 4; nbl++) {
        int nb = wg * 4 + nbl;
        uint32_t r[32];
        ldtm32(r, tmem + nb * 32);
#pragma unroll
        for (int j = 0; j < 8; j++) {
            float4 xr = *(const float4*)(x + base + nb * 32 + 4 * j);
            float4 v;
            v.x = __uint_as_float(r[4 * j + 0]) + bias + xr.x;
            v.y = __uint_as_float(r[4 * j + 1]) + bias + xr.y;
            v.z = __uint_as_float(r[4 * j + 2]) + bias + xr.z;
            v.w = __uint_as_float(r[4 * j + 3]) + bias + xr.w;
            *(float4*)(out + base + nb * 32 + 4 * j) = v;
        }
    }
    gemm_dealloc(tmem);
}

// ---------------- launch ----------------
extern "C" void kernel_launch(void* const* d_in, const int* in_sizes, int n_in,
                              void* d_out, int out_size) {
    const float* x     = (const float*)d_in[0];
    const float* gamma = (const float*)d_in[1];
    const float* beta  = (const float*)d_in[2];
    const float* wq    = (const float*)d_in[3];
    const float* bq    = (const float*)d_in[4];
    const float* wk    = (const float*)d_in[5];
    const float* bk    = (const float*)d_in[6];
    const float* wv    = (const float*)d_in[7];
    const float* bv    = (const float*)d_in[8];
    const float* wp    = (const float*)d_in[9];
    const float* bp    = (const float*)d_in[10];
    float* out = (float*)d_out;

    cudaFuncSetAttribute(qk_gemm_tc,     cudaFuncAttributeMaxDynamicSharedMemorySize, SMEMSZ);
    cudaFuncSetAttribute(v_gemm_tc,      cudaFuncAttributeMaxDynamicSharedMemorySize, SMEMSZ);
    cudaFuncSetAttribute(scores_gemm_tc, cudaFuncAttributeMaxDynamicSharedMemorySize, SMEMSZ);
    cudaFuncSetAttribute(av_gemm_tc,     cudaFuncAttributeMaxDynamicSharedMemorySize, SMEMSZ);
    cudaFuncSetAttribute(proj_gemm_tc,   cudaFuncAttributeMaxDynamicSharedMemorySize, SMEMSZ);

    bn_stats<<<C, 256>>>(x, gamma, beta);
    split_weights<<<dim3((C * C / 2) / 256, 4), 256>>>(wq, wk, wv, wp);
    prep_xsplit<<<dim3(L / 32, C / 32, BB), dim3(32, 8)>>>(x);
    qk_gemm_tc<<<dim3(L / 128, BB * 2), 256, SMEMSZ>>>(bq, bk);
    split_qk<<<dim3((int)(((size_t)BB * L * C / 2) / 256), 2), 256>>>();
    v_gemm_tc<<<dim3(L / 256, C / 128, BB), 256, SMEMSZ>>>(bv);
    split_v<<<(int)(((size_t)BB * C * L / 2) / 256), 256>>>();
    scores_gemm_tc<<<dim3(L / 256, L / 128, BB), 256, SMEMSZ>>>();
    softmax_rows<<<BB * L, 256>>>();
    av_gemm_tc<<<dim3(L / 128, BB), 256, SMEMSZ>>>();
    transpose_split_h<<<dim3(L / 32, C / 32, BB), dim3(32, 8)>>>();
    proj_gemm_tc<<<dim3(L / 256, C / 128, BB), 256, SMEMSZ>>>(x, bp, out);
}

// round 10
// speedup vs baseline: 6.2491x; 1.3796x over previous
#include <cuda_runtime.h>
#include <cuda_bf16.h>
#include <cstdint>

#define BB 4
#define C 256
#define L 4096
#define EPSV 1e-5f
#define NSPLIT 4

#if defined(__CUDA_ARCH_FEAT_SM103_ALL) || defined(__CUDA_ARCH_FEAT_SM100_ALL) || defined(__CUDA_ARCH_FAMILY_SPECIFIC__)
#define TC_OK 1
#else
#define TC_OK 0
#endif

// ---------------- device scratch ----------------
__device__ float g_scale[C];
__device__ float g_shift[C];
__device__ __align__(16) __nv_bfloat16 g_wbh[4 * C * C], g_wbl[4 * C * C];
__device__ __align__(16) __nv_bfloat16 g_xth[(size_t)BB * L * C], g_xtl[(size_t)BB * L * C];
__device__ float g_s[(size_t)BB * L * L];
__device__ float g_hp[NSPLIT][(size_t)BB * C * L];   // AV split-K partials
__device__ __align__(16) __nv_bfloat16 g_qh[(size_t)BB * L * C], g_ql[(size_t)BB * L * C];
__device__ __align__(16) __nv_bfloat16 g_kh[(size_t)BB * L * C], g_kl[(size_t)BB * L * C];
__device__ __align__(16) __nv_bfloat16 g_vh[(size_t)BB * C * L], g_vl[(size_t)BB * C * L];
__device__ __align__(16) __nv_bfloat16 g_ph[(size_t)BB * L * L], g_pl[(size_t)BB * L * L];
__device__ __align__(16) __nv_bfloat16 g_hth[(size_t)BB * L * C], g_htl[(size_t)BB * L * C];

// ---------------- SMEM layout ----------------
#define SM_PTR   0
#define SM_MBAR0 8
#define SM_MBAR1 16
#define SM_A     1024
#define SM_B     (1024 + 32768)
#define SMEMSZ   (1024 + 32768 + 65536)

#define IDESC_BF16 0x8400490u

// ---------------- fold-proof bf16 hi/lo split ----------------
__device__ __forceinline__ void split_bf16(float v, uint16_t& hb, uint16_t& lb) {
    float hf, r;
    asm("cvt.rn.bf16.f32 %0, %1;" : "=h"(hb) : "f"(v));
    asm("cvt.f32.bf16 %0, %1;"    : "=f"(hf) : "h"(hb));
    asm("sub.rn.f32 %0, %1, %2;"  : "=f"(r)  : "f"(v), "f"(hf));
    asm("cvt.rn.bf16.f32 %0, %1;" : "=h"(lb) : "f"(r));
}
__device__ __forceinline__ void wsplit2(__nv_bfloat16* h, __nv_bfloat16* l, size_t idx,
                                        float a, float b) {
    uint16_t ha, la, hbb, lbb;
    split_bf16(a, ha, la);
    split_bf16(b, hbb, lbb);
    uint32_t hp = (uint32_t)ha | ((uint32_t)hbb << 16);
    uint32_t lp = (uint32_t)la | ((uint32_t)lbb << 16);
    *(uint32_t*)((char*)h + idx * 2) = hp;
    *(uint32_t*)((char*)l + idx * 2) = lp;
}

// ---------------- tcgen05 helpers ----------------
__device__ __forceinline__ uint32_t smem_u32(const void* p) {
    uint32_t a;
    asm("{ .reg .u64 t; cvta.to.shared.u64 t, %1; cvt.u32.u64 %0, t; }" : "=r"(a) : "l"(p));
    return a;
}
__device__ __forceinline__ uint32_t elect1() {
    uint32_t p;
    asm volatile("{\n\t.reg .pred p;\n\telect.sync _|p, 0xFFFFFFFF;\n\tselp.b32 %0, 1, 0, p;\n\t}" : "=r"(p));
    return p;
}
__device__ __forceinline__ uint64_t make_desc(uint32_t addr) {
    return (2ULL << 61) | (1ULL << 46) | (64ULL << 32) | (1ULL << 16) |
           ((uint64_t)(addr >> 4) & 0x3FFF);
}
__device__ __forceinline__ void tc_alloc(uint32_t sptr) {
#if TC_OK
    asm volatile("tcgen05.alloc.cta_group::1.sync.aligned.shared::cta.b32 [%0], %1;"
                 :: "r"(sptr), "r"(256u) : "memory");
    asm volatile("tcgen05.relinquish_alloc_permit.cta_group::1.sync.aligned;");
#endif
}
__device__ __forceinline__ void tc_dealloc(uint32_t tmem) {
#if TC_OK
    asm volatile("tcgen05.dealloc.cta_group::1.sync.aligned.b32 %0, %1;" :: "r"(tmem), "r"(256u));
#endif
}
__device__ __forceinline__ void mma_bf16(uint32_t d, uint64_t ad, uint64_t bd, bool acc) {
#if TC_OK
    uint32_t e = acc ? 1u : 0u;
    asm volatile(
        "{\n\t.reg .pred p;\n\tsetp.ne.u32 p, %4, 0;\n\t"
        "tcgen05.mma.cta_group::1.kind::f16 [%0], %1, %2, %3, {%5, %5, %5, %5}, p;\n\t}"
        :: "r"(d), "l"(ad), "l"(bd), "r"(IDESC_BF16), "r"(e), "r"(0u) : "memory");
#endif
}
__device__ __forceinline__ void tc_commit(uint32_t mbar) {
#if TC_OK
    asm volatile("tcgen05.commit.cta_group::1.mbarrier::arrive::one.shared::cluster.b64 [%0];"
                 :: "r"(mbar) : "memory");
#endif
}
__device__ __forceinline__ void tc_fence_after() {
#if TC_OK
    asm volatile("tcgen05.fence::after_thread_sync;" ::: "memory");
#endif
}
__device__ __forceinline__ void ldtm32(uint32_t* r, uint32_t addr) {
#if TC_OK
    asm volatile(
        "tcgen05.ld.sync.aligned.32x32b.x32.b32 "
        "{%0, %1, %2, %3, %4, %5, %6, %7, "
        " %8, %9, %10, %11, %12, %13, %14, %15, "
        " %16, %17, %18, %19, %20, %21, %22, %23, "
        " %24, %25, %26, %27, %28, %29, %30, %31}, [%32];"
        : "=r"(r[0]),  "=r"(r[1]),  "=r"(r[2]),  "=r"(r[3]),
          "=r"(r[4]),  "=r"(r[5]),  "=r"(r[6]),  "=r"(r[7]),
          "=r"(r[8]),  "=r"(r[9]),  "=r"(r[10]), "=r"(r[11]),
          "=r"(r[12]), "=r"(r[13]), "=r"(r[14]), "=r"(r[15]),
          "=r"(r[16]), "=r"(r[17]), "=r"(r[18]), "=r"(r[19]),
          "=r"(r[20]), "=r"(r[21]), "=r"(r[22]), "=r"(r[23]),
          "=r"(r[24]), "=r"(r[25]), "=r"(r[26]), "=r"(r[27]),
          "=r"(r[28]), "=r"(r[29]), "=r"(r[30]), "=r"(r[31])
        : "r"(addr));
    asm volatile("tcgen05.wait::ld.sync.aligned;" ::: "memory");
#else
#pragma unroll
    for (int i = 0; i < 32; i++) r[i] = 0;
#endif
}
__device__ __forceinline__ void mbar_init(uint32_t a) {
    asm volatile("mbarrier.init.shared.b64 [%0], %1;" :: "r"(a), "r"(1u) : "memory");
}
__device__ __forceinline__ void mbar_wait(uint32_t a, int parity) {
    asm volatile(
        "{\n\t.reg .pred P;\n"
        "W_%=:\n\t"
        "mbarrier.try_wait.parity.acquire.cta.shared::cta.b64 P, [%0], %1, 0x989680;\n\t"
        "@P bra.uni D_%=;\n\t"
        "bra.uni W_%=;\n"
        "D_%=:\n\t}"
        :: "r"(a), "r"(parity) : "memory");
}

// ---------------- cp.async tile loader (256 threads, SW128) ----------------
__device__ __forceinline__ void cpa_tiles(const __nv_bfloat16* __restrict__ A, int lda,
                                          const __nv_bfloat16* __restrict__ B, int ldb,
                                          int k0, uint32_t da, uint32_t db, int t) {
#pragma unroll
    for (int i = 0; i < 4; i++) {
        int idx = t + i * 256;
        int r = idx >> 3, cc = idx & 7;
        uint32_t off = r * 128 + cc * 16;
        asm volatile("cp.async.cg.shared.global [%0], [%1], 16;"
                     :: "r"(da + (off ^ ((off >> 3) & 0x70))),
                        "l"(A + (size_t)r * lda + k0 + cc * 8) : "memory");
    }
#pragma unroll
    for (int i = 0; i < 8; i++) {
        int idx = t + i * 256;
        int r = idx >> 3, cc = idx & 7;
        uint32_t off = r * 128 + cc * 16;
        asm volatile("cp.async.cg.shared.global [%0], [%1], 16;"
                     :: "r"(db + (off ^ ((off >> 3) & 0x70))),
                        "l"(B + (size_t)r * ldb + k0 + cc * 8) : "memory");
    }
}

__device__ __forceinline__ void seg_sel(const __nv_bfloat16* Ah, const __nv_bfloat16* Al,
                                        const __nv_bfloat16* Bh, const __nv_bfloat16* Bl,
                                        int ck, int nseg,
                                        const __nv_bfloat16*& Ap, const __nv_bfloat16*& Bp, int& k0) {
    int seg = (ck >= nseg) + (ck >= 2 * nseg);
    Ap = (seg == 1) ? Al : Ah;
    Bp = (seg == 2) ? Bl : Bh;
    k0 = (ck - seg * nseg) * 64;
}

// D[128x256] = Ah*Bh^T + Al*Bh^T + Ah*Bl^T   (cp.async double-buffer pipeline)
__device__ __forceinline__ uint32_t run_gemm3(const __nv_bfloat16* __restrict__ Ah,
                                              const __nv_bfloat16* __restrict__ Al,
                                              const __nv_bfloat16* __restrict__ Bh,
                                              const __nv_bfloat16* __restrict__ Bl,
                                              int lda, int ldb, int nseg, char* smem) {
    const int t = threadIdx.x;
    const int nch = 3 * nseg;
    uint32_t sb = smem_u32(smem);
    if (t < 32) tc_alloc(sb + SM_PTR);
    if (t == 0) { mbar_init(sb + SM_MBAR0); mbar_init(sb + SM_MBAR1); }
    __syncthreads();
    uint32_t tmem;
    asm volatile("ld.shared.b32 %0, [%1];" : "=r"(tmem) : "r"(sb + SM_PTR));

    int ph0 = 0, ph1 = 0;
    cpa_tiles(Ah, lda, Bh, ldb, 0, sb + SM_A, sb + SM_B, t);
    asm volatile("cp.async.commit_group;" ::: "memory");

    for (int ck = 0; ck < nch; ck++) {
        const int pb = ck & 1;
        if (ck + 1 < nch) {
            const int nb = pb ^ 1;
            if (ck >= 1) {
                if (nb == 0) { mbar_wait(sb + SM_MBAR0, ph0); ph0 ^= 1; }
                else         { mbar_wait(sb + SM_MBAR1, ph1); ph1 ^= 1; }
            }
            const __nv_bfloat16 *Ap, *Bp;
            int k0;
            seg_sel(Ah, Al, Bh, Bl, ck + 1, nseg, Ap, Bp, k0);
            cpa_tiles(Ap, lda, Bp, ldb, k0,
                      sb + SM_A + nb * 16384, sb + SM_B + nb * 32768, t);
            asm volatile("cp.async.commit_group;" ::: "memory");
            asm volatile("cp.async.wait_group 1;" ::: "memory");   // chunk ck resident
        } else {
            asm volatile("cp.async.wait_group 0;" ::: "memory");
        }
        __syncthreads();
        if (t < 32) {
            asm volatile("fence.proxy.async.shared::cta;" ::: "memory");
            if (elect1()) {
                uint64_t ad = make_desc(sb + SM_A + pb * 16384);
                uint64_t bd = make_desc(sb + SM_B + pb * 32768);
#pragma unroll
                for (int s = 0; s < 4; s++)
                    mma_bf16(tmem, ad + 2 * s, bd + 2 * s, (ck | s) != 0);
                tc_commit(sb + SM_MBAR0 + pb * 8);
            }
        }
    }
    if (((nch - 1) & 1) == 0) mbar_wait(sb + SM_MBAR0, ph0);
    else                      mbar_wait(sb + SM_MBAR1, ph1);
    tc_fence_after();
    return tmem;
}

__device__ __forceinline__ void gemm_dealloc(uint32_t tmem) {
    __syncthreads();
    if (threadIdx.x < 32) tc_dealloc(tmem);
}

// ---------------- 1) BN stats ----------------
__global__ void __launch_bounds__(256) bn_stats(const float* __restrict__ x,
                                                const float* __restrict__ gamma,
                                                const float* __restrict__ beta) {
    int c = blockIdx.x, t = threadIdx.x;
    float s = 0.f, sq = 0.f;
    for (int b = 0; b < BB; b++) {
        const float* p = x + ((size_t)b * C + c) * L;
        for (int l = t; l < L; l += 256) { float v = p[l]; s += v; sq += v * v; }
    }
    __shared__ float sh0[256], sh1[256];
    sh0[t] = s; sh1[t] = sq;
    __syncthreads();
    for (int o = 128; o > 0; o >>= 1) {
        if (t < o) { sh0[t] += sh0[t + o]; sh1[t] += sh1[t + o]; }
        __syncthreads();
    }
    if (t == 0) {
        const float inv_n = 1.f / (float)(BB * L);
        float mean = sh0[0] * inv_n;
        float var  = sh1[0] * inv_n - mean * mean;
        float rs   = rsqrtf(var + EPSV);
        float sc   = gamma[c] * rs;
        g_scale[c] = sc;
        g_shift[c] = beta[c] - mean * sc;
    }
}

// ---------------- 2) split RAW weights ----------------
__global__ void __launch_bounds__(256) split_weights(const float* __restrict__ wq,
                                                     const float* __restrict__ wk,
                                                     const float* __restrict__ wv,
                                                     const float* __restrict__ wp) {
    int mat = blockIdx.y;
    const float* w = (mat == 0) ? wq : ((mat == 1) ? wk : ((mat == 2) ? wv : wp));
    size_t i = ((size_t)blockIdx.x * 256 + threadIdx.x) * 2;
    float2 v = *(const float2*)(w + i);
    wsplit2(g_wbh + (size_t)mat * C * C, g_wbl + (size_t)mat * C * C, i, v.x, v.y);
}

// ---------------- 3) normalize + transpose + split x ----------------
__global__ void __launch_bounds__(256) prep_xsplit(const float* __restrict__ x) {
    __shared__ float tile[32][33];
    int bi = blockIdx.z;
    int l0 = blockIdx.x * 32, c0 = blockIdx.y * 32;
    int tx = threadIdx.x, ty = threadIdx.y;
#pragma unroll
    for (int j = 0; j < 4; j++) {
        int c = c0 + ty + j * 8;
        float v = x[((size_t)bi * C + c) * L + l0 + tx];
        tile[ty + j * 8][tx] = v * g_scale[c] + g_shift[c];
    }
    __syncthreads();
#pragma unroll
    for (int j = 0; j < 4; j++) {
        int l = l0 + ty + j * 8;
        float v = tile[tx][ty + j * 8];
        uint16_t hb, lb;
        split_bf16(v, hb, lb);
        size_t idx = ((size_t)bi * L + l) * C + c0 + tx;
        *(uint16_t*)&g_xth[idx] = hb;
        *(uint16_t*)&g_xtl[idx] = lb;
    }
}

// ---------------- 4) q/k TC projection, fused split epilogue ----------------
__global__ void __launch_bounds__(256) qk_gemm_tc(const float* __restrict__ bq,
                                                  const float* __restrict__ bk) {
    extern __shared__ char smem[];
    int bi = blockIdx.y >> 1, mat = blockIdx.y & 1;
    int l0 = blockIdx.x * 128;
    size_t arow = ((size_t)bi * L + l0) * C;
    uint32_t tmem = run_gemm3(g_xth + arow, g_xtl + arow,
                              g_wbh + (size_t)mat * C * C, g_wbl + (size_t)mat * C * C, C, C, 4, smem);

    int t = threadIdx.x, wt = t & 127, wg = t >> 7;
    size_t drow = ((size_t)bi * L + l0 + wt) * C;
    __nv_bfloat16* dh = mat ? g_kh : g_qh;
    __nv_bfloat16* dl = mat ? g_kl : g_ql;
    const float* bias = mat ? bk : bq;
    for (int nbl = 0; nbl < 4; nbl++) {
        int nb = wg * 4 + nbl;
        uint32_t r[32];
        ldtm32(r, tmem + nb * 32);
#pragma unroll
        for (int j = 0; j < 16; j++) {
            int n = nb * 32 + 2 * j;
            wsplit2(dh, dl, drow + n, __uint_as_float(r[2 * j + 0]) + bias[n + 0],
                                      __uint_as_float(r[2 * j + 1]) + bias[n + 1]);
        }
    }
    gemm_dealloc(tmem);
}

// ---------------- 5) v TC projection, fused split epilogue ----------------
__global__ void __launch_bounds__(256) v_gemm_tc(const float* __restrict__ bv) {
    extern __shared__ char smem[];
    int bi = blockIdx.z, o0 = blockIdx.y * 128, l0 = blockIdx.x * 256;
    size_t brow = ((size_t)bi * L + l0) * C;
    uint32_t tmem = run_gemm3(g_wbh + 2 * C * C + o0 * C, g_wbl + 2 * C * C + o0 * C,
                              g_xth + brow, g_xtl + brow, C, C, 4, smem);

    int t = threadIdx.x, wt = t & 127, wg = t >> 7;
    float bias = bv[o0 + wt];
    size_t drow = ((size_t)bi * C + o0 + wt) * L + l0;
    for (int nbl = 0; nbl < 4; nbl++) {
        int nb = wg * 4 + nbl;
        uint32_t r[32];
        ldtm32(r, tmem + nb * 32);
#pragma unroll
        for (int j = 0; j < 16; j++) {
            int n = nb * 32 + 2 * j;
            wsplit2(g_vh, g_vl, drow + n, __uint_as_float(r[2 * j + 0]) + bias,
                                          __uint_as_float(r[2 * j + 1]) + bias);
        }
    }
    gemm_dealloc(tmem);
}

// ---------------- 6) scores TC ----------------
__global__ void __launch_bounds__(256) scores_gemm_tc() {
    extern __shared__ char smem[];
    int bi = blockIdx.z, i0 = blockIdx.y * 128, j0 = blockIdx.x * 256;
    size_t arow = ((size_t)bi * L + i0) * C;
    size_t brow = ((size_t)bi * L + j0) * C;
    uint32_t tmem = run_gemm3(g_qh + arow, g_ql + arow, g_kh + brow, g_kl + brow, C, C, 4, smem);

    int t = threadIdx.x, wt = t & 127, wg = t >> 7;
    float* dst = g_s + ((size_t)bi * L + i0 + wt) * L + j0;
    const float scale = 0.0625f;
    for (int nbl = 0; nbl < 4; nbl++) {
        int nb = wg * 4 + nbl;
        uint32_t r[32];
        ldtm32(r, tmem + nb * 32);
#pragma unroll
        for (int j = 0; j < 8; j++) {
            float4 v;
            v.x = __uint_as_float(r[4 * j + 0]) * scale;
            v.y = __uint_as_float(r[4 * j + 1]) * scale;
            v.z = __uint_as_float(r[4 * j + 2]) * scale;
            v.w = __uint_as_float(r[4 * j + 3]) * scale;
            *(float4*)(dst + nb * 32 + 4 * j) = v;
        }
    }
    gemm_dealloc(tmem);
}

// ---------------- 7) softmax rows -> ph/pl ----------------
__global__ void __launch_bounds__(256) softmax_rows() {
    size_t row = blockIdx.x;
    const float* p = g_s + row * (size_t)L;
    const int t = threadIdx.x;
    float2 r[8];
    float mx = -1e30f;
#pragma unroll
    for (int i = 0; i < 8; i++) {
        r[i] = *(const float2*)(p + i * 512 + t * 2);
        mx = fmaxf(mx, fmaxf(r[i].x, r[i].y));
    }
#pragma unroll
    for (int o = 16; o; o >>= 1) mx = fmaxf(mx, __shfl_xor_sync(0xffffffffu, mx, o));
    __shared__ float sm[8];
    if ((t & 31) == 0) sm[t >> 5] = mx;
    __syncthreads();
    float bm = sm[0];
#pragma unroll
    for (int i = 1; i < 8; i++) bm = fmaxf(bm, sm[i]);
    float s = 0.f;
#pragma unroll
    for (int i = 0; i < 8; i++) {
        r[i].x = __expf(r[i].x - bm);
        r[i].y = __expf(r[i].y - bm);
        s += r[i].x + r[i].y;
    }
#pragma unroll
    for (int o = 16; o; o >>= 1) s += __shfl_xor_sync(0xffffffffu, s, o);
    __syncthreads();
    if ((t & 31) == 0) sm[t >> 5] = s;
    __syncthreads();
    float tot = 0.f;
#pragma unroll
    for (int i = 0; i < 8; i++) tot += sm[i];
    float inv = 1.f / tot;
    size_t base = row * (size_t)L;
#pragma unroll
    for (int i = 0; i < 8; i++)
        wsplit2(g_ph, g_pl, base + i * 512 + t * 2, r[i].x * inv, r[i].y * inv);
}

// ---------------- 8) AV TC, split-K: partial fp32 h[c][l] per split ----------------
__global__ void __launch_bounds__(256) av_gemm_tc() {
    extern __shared__ char smem[];
    int bi = blockIdx.z, ks = blockIdx.y, i0 = blockIdx.x * 128;
    const int koff = ks * (L / NSPLIT);      // 1024 elements of K
    size_t arow = ((size_t)bi * L + i0) * L + koff;
    size_t brow = (size_t)bi * C * L + koff;
    uint32_t tmem = run_gemm3(g_ph + arow, g_pl + arow, g_vh + brow, g_vl + brow,
                              L, L, (L / NSPLIT) / 64, smem);

    int t = threadIdx.x, wt = t & 127, wg = t >> 7;
    float* hb = g_hp[ks] + (size_t)bi * C * L;
    for (int nbl = 0; nbl < 4; nbl++) {
        int nb = wg * 4 + nbl;
        uint32_t r[32];
        ldtm32(r, tmem + nb * 32);
#pragma unroll
        for (int j = 0; j < 32; j++) {
            int c = nb * 32 + j;
            hb[(size_t)c * L + i0 + wt] = __uint_as_float(r[j]);
        }
    }
    gemm_dealloc(tmem);
}

// ---------------- 9) reduce partials + transpose + split h ----------------
__global__ void __launch_bounds__(256) reduce_split_h() {
    __shared__ float tile[32][33];
    int bi = blockIdx.z;
    int l0 = blockIdx.x * 32, c0 = blockIdx.y * 32;
    int tx = threadIdx.x, ty = threadIdx.y;
#pragma unroll
    for (int j = 0; j < 4; j++) {
        int c = c0 + ty + j * 8;
        size_t idx = ((size_t)bi * C + c) * L + l0 + tx;
        float s = g_hp[0][idx] + g_hp[1][idx] + g_hp[2][idx] + g_hp[3][idx];
        tile[ty + j * 8][tx] = s;
    }
    __syncthreads();
#pragma unroll
    for (int j = 0; j < 4; j++) {
        int l = l0 + ty + j * 8;
        float v = tile[tx][ty + j * 8];
        uint16_t hb, lb;
        split_bf16(v, hb, lb);
        size_t idx = ((size_t)bi * L + l) * C + c0 + tx;
        *(uint16_t*)&g_hth[idx] = hb;
        *(uint16_t*)&g_htl[idx] = lb;
    }
}

// ---------------- 10) proj TC + bias + residual ----------------
__global__ void __launch_bounds__(256) proj_gemm_tc(const float* __restrict__ x,
                                                    const float* __restrict__ bp,
                                                    float* __restrict__ out) {
    extern __shared__ char smem[];
    int bi = blockIdx.z, o0 = blockIdx.y * 128, l0 = blockIdx.x * 256;
    size_t brow = ((size_t)bi * L + l0) * C;
    uint32_t tmem = run_gemm3(g_wbh + 3 * C * C + o0 * C, g_wbl + 3 * C * C + o0 * C,
                              g_hth + brow, g_htl + brow, C, C, 4, smem);

    int t = threadIdx.x, wt = t & 127, wg = t >> 7;
    float bias = bp[o0 + wt];
    size_t base = ((size_t)bi * C + o0 + wt) * L + l0;
    for (int nbl = 0; nbl < 4; nbl++) {
        int nb = wg * 4 + nbl;
        uint32_t r[32];
        ldtm32(r, tmem + nb * 32);
#pragma unroll
        for (int j = 0; j < 8; j++) {
            float4 xr = *(const float4*)(x + base + nb * 32 + 4 * j);
            float4 v;
            v.x = __uint_as_float(r[4 * j + 0]) + bias + xr.x;
            v.y = __uint_as_float(r[4 * j + 1]) + bias + xr.y;
            v.z = __uint_as_float(r[4 * j + 2]) + bias + xr.z;
            v.w = __uint_as_float(r[4 * j + 3]) + bias + xr.w;
            *(float4*)(out + base + nb * 32 + 4 * j) = v;
        }
    }
    gemm_dealloc(tmem);
}

// ---------------- launch ----------------
extern "C" void kernel_launch(void* const* d_in, const int* in_sizes, int n_in,
                              void* d_out, int out_size) {
    const float* x     = (const float*)d_in[0];
    const float* gamma = (const float*)d_in[1];
    const float* beta  = (const float*)d_in[2];
    const float* wq    = (const float*)d_in[3];
    const float* bq    = (const float*)d_in[4];
    const float* wk    = (const float*)d_in[5];
    const float* bk    = (const float*)d_in[6];
    const float* wv    = (const float*)d_in[7];
    const float* bv    = (const float*)d_in[8];
    const float* wp    = (const float*)d_in[9];
    const float* bp    = (const float*)d_in[10];
    float* out = (float*)d_out;

    cudaFuncSetAttribute(qk_gemm_tc,     cudaFuncAttributeMaxDynamicSharedMemorySize, SMEMSZ);
    cudaFuncSetAttribute(v_gemm_tc,      cudaFuncAttributeMaxDynamicSharedMemorySize, SMEMSZ);
    cudaFuncSetAttribute(scores_gemm_tc, cudaFuncAttributeMaxDynamicSharedMemorySize, SMEMSZ);
    cudaFuncSetAttribute(av_gemm_tc,     cudaFuncAttributeMaxDynamicSharedMemorySize, SMEMSZ);
    cudaFuncSetAttribute(proj_gemm_tc,   cudaFuncAttributeMaxDynamicSharedMemorySize, SMEMSZ);

    bn_stats<<<C, 256>>>(x, gamma, beta);
    split_weights<<<dim3((C * C / 2) / 256, 4), 256>>>(wq, wk, wv, wp);
    prep_xsplit<<<dim3(L / 32, C / 32, BB), dim3(32, 8)>>>(x);
    qk_gemm_tc<<<dim3(L / 128, BB * 2), 256, SMEMSZ>>>(bq, bk);
    v_gemm_tc<<<dim3(L / 256, C / 128, BB), 256, SMEMSZ>>>(bv);
    scores_gemm_tc<<<dim3(L / 256, L / 128, BB), 256, SMEMSZ>>>();
    softmax_rows<<<BB * L, 256>>>();
    av_gemm_tc<<<dim3(L / 128, NSPLIT, BB), 256, SMEMSZ>>>();
    reduce_split_h<<<dim3(L / 32, C / 32, BB), dim3(32, 8)>>>();
    proj_gemm_tc<<<dim3(L / 256, C / 128, BB), 256, SMEMSZ>>>(x, bp, out);
}